// round 1
// baseline (speedup 1.0000x reference)
#include <cuda_runtime.h>
#include <math.h>

#define NIN  32
#define NH   64
#define NOUT 3

// shared-memory float offsets
#define OFF_W0 0        // 64*32 = 2048
#define OFF_B0 2048     // 64
#define OFF_W1 2112     // 64*64 = 4096
#define OFF_B1 6208     // 64
#define OFF_W2 6272     // 4096
#define OFF_B2 10368    // 64
#define OFF_W3 10432    // 4096
#define OFF_B3 14528    // 64
#define OFF_W4 14592    // 3*64 = 192
#define OFF_B4 14784    // 3
#define SMEM_FLOATS 14787
#define SMEM_BYTES (SMEM_FLOATS * 4)

#define THREADS 128
#define BLOCKS  (148 * 8)

__device__ __forceinline__ void copy_sm(float* dst, const float* __restrict__ src, int cnt) {
    for (int i = threadIdx.x; i < cnt; i += blockDim.x) dst[i] = src[i];
}

// 64 -> 64 hidden layer with ReLU. src/dst are register arrays (fully static
// indexing after unroll), W/b live in shared memory (broadcast LDS).
__device__ __forceinline__ void layer64(float* __restrict__ dst, const float* __restrict__ src,
                                        const float* __restrict__ W, const float* __restrict__ b) {
#pragma unroll
    for (int j = 0; j < NH; j++) {
        const float* w = W + j * NH;
        float a0 = 0.f, a1 = 0.f, a2 = 0.f, a3 = 0.f;
#pragma unroll
        for (int k = 0; k < NH; k += 4) {
            a0 = fmaf(w[k + 0], src[k + 0], a0);
            a1 = fmaf(w[k + 1], src[k + 1], a1);
            a2 = fmaf(w[k + 2], src[k + 2], a2);
            a3 = fmaf(w[k + 3], src[k + 3], a3);
        }
        float v = (a0 + a1) + (a2 + a3) + b[j];
        dst[j] = v > 0.f ? v : 0.f;
    }
}

__global__ __launch_bounds__(THREADS)
void mlp_fused_kernel(const float* __restrict__ x,
                      const float* __restrict__ W0, const float* __restrict__ b0,
                      const float* __restrict__ W1, const float* __restrict__ b1,
                      const float* __restrict__ W2, const float* __restrict__ b2,
                      const float* __restrict__ W3, const float* __restrict__ b3,
                      const float* __restrict__ W4, const float* __restrict__ b4,
                      float* __restrict__ out, int n) {
    extern __shared__ float sm[];
    copy_sm(sm + OFF_W0, W0, NH * NIN);
    copy_sm(sm + OFF_B0, b0, NH);
    copy_sm(sm + OFF_W1, W1, NH * NH);
    copy_sm(sm + OFF_B1, b1, NH);
    copy_sm(sm + OFF_W2, W2, NH * NH);
    copy_sm(sm + OFF_B2, b2, NH);
    copy_sm(sm + OFF_W3, W3, NH * NH);
    copy_sm(sm + OFF_B3, b3, NH);
    copy_sm(sm + OFF_W4, W4, NOUT * NH);
    copy_sm(sm + OFF_B4, b4, NOUT);
    __syncthreads();

    const float* sW0 = sm + OFF_W0;
    const float* sb0 = sm + OFF_B0;
    const float* sW1 = sm + OFF_W1;
    const float* sb1 = sm + OFF_B1;
    const float* sW2 = sm + OFF_W2;
    const float* sb2 = sm + OFF_B2;
    const float* sW3 = sm + OFF_W3;
    const float* sb3 = sm + OFF_B3;
    const float* sW4 = sm + OFF_W4;
    const float* sb4 = sm + OFF_B4;

    const int stride = gridDim.x * blockDim.x;
    for (int r = blockIdx.x * blockDim.x + threadIdx.x; r < n; r += stride) {
        // load the 32-float input row (vectorized; each thread reads its own 128B)
        float xv[NIN];
        const float4* xp = reinterpret_cast<const float4*>(x + (size_t)r * NIN);
#pragma unroll
        for (int q = 0; q < NIN / 4; q++) {
            float4 v = xp[q];
            xv[4 * q + 0] = v.x;
            xv[4 * q + 1] = v.y;
            xv[4 * q + 2] = v.z;
            xv[4 * q + 3] = v.w;
        }

        float h[NH], g[NH];

        // layer 0: 32 -> 64, ReLU
#pragma unroll
        for (int j = 0; j < NH; j++) {
            const float* w = sW0 + j * NIN;
            float a0 = 0.f, a1 = 0.f, a2 = 0.f, a3 = 0.f;
#pragma unroll
            for (int k = 0; k < NIN; k += 4) {
                a0 = fmaf(w[k + 0], xv[k + 0], a0);
                a1 = fmaf(w[k + 1], xv[k + 1], a1);
                a2 = fmaf(w[k + 2], xv[k + 2], a2);
                a3 = fmaf(w[k + 3], xv[k + 3], a3);
            }
            float v = (a0 + a1) + (a2 + a3) + sb0[j];
            h[j] = v > 0.f ? v : 0.f;
        }

        // hidden layers 1..3: 64 -> 64, ReLU (ping-pong register arrays)
        layer64(g, h, sW1, sb1);
        layer64(h, g, sW2, sb2);
        layer64(g, h, sW3, sb3);

        // output layer: 64 -> 3, sigmoid
        float o[NOUT];
#pragma unroll
        for (int j = 0; j < NOUT; j++) {
            const float* w = sW4 + j * NH;
            float a0 = 0.f, a1 = 0.f, a2 = 0.f, a3 = 0.f;
#pragma unroll
            for (int k = 0; k < NH; k += 4) {
                a0 = fmaf(w[k + 0], g[k + 0], a0);
                a1 = fmaf(w[k + 1], g[k + 1], a1);
                a2 = fmaf(w[k + 2], g[k + 2], a2);
                a3 = fmaf(w[k + 3], g[k + 3], a3);
            }
            float v = (a0 + a1) + (a2 + a3) + sb4[j];
            o[j] = 1.f / (1.f + expf(-v));
        }

        float* op = out + (size_t)r * NOUT;
        op[0] = o[0];
        op[1] = o[1];
        op[2] = o[2];
    }
}

extern "C" void kernel_launch(void* const* d_in, const int* in_sizes, int n_in,
                              void* d_out, int out_size) {
    const float* x  = (const float*)d_in[0];
    const float* W0 = (const float*)d_in[1];
    const float* b0 = (const float*)d_in[2];
    const float* W1 = (const float*)d_in[3];
    const float* b1 = (const float*)d_in[4];
    const float* W2 = (const float*)d_in[5];
    const float* b2 = (const float*)d_in[6];
    const float* W3 = (const float*)d_in[7];
    const float* b3 = (const float*)d_in[8];
    const float* W4 = (const float*)d_in[9];
    const float* b4 = (const float*)d_in[10];
    float* out = (float*)d_out;

    const int n = in_sizes[0] / NIN;

    // >48KB dynamic smem requires opt-in (idempotent, capture-safe: not a stream op)
    cudaFuncSetAttribute(mlp_fused_kernel,
                         cudaFuncAttributeMaxDynamicSharedMemorySize, SMEM_BYTES);

    int blocks = BLOCKS;
    int needed = (n + THREADS - 1) / THREADS;
    if (needed < blocks) blocks = needed;

    mlp_fused_kernel<<<blocks, THREADS, SMEM_BYTES>>>(
        x, W0, b0, W1, b1, W2, b2, W3, b3, W4, b4, out, n);
}

// round 3
// speedup vs baseline: 6.4232x; 6.4232x over previous
#include <cuda_runtime.h>
#include <cuda_fp16.h>
#include <stdint.h>
#include <math.h>

// ---------------------------------------------------------------------------
// Fused 5-layer MLP (32->64->64->64->64->3, ReLU hidden, sigmoid out).
// Tensor path: warp-level mma.sync m16n8k16 fp16 with split-fp16 (hi+lo)
// 3-pass accumulation in fp32 for fp32-grade precision (baseline PTX; no
// sm_100a-only instructions).
//
// Layout insight: the mma.sync D-fragment column/row ownership per thread is
// identical to the A-fragment ownership for the NEXT layer, so activations
// stay in registers across all 4 hidden layers (pure register repack between
// layers). Only weights are read (from padded SMEM, conflict-free).
// Each warp: 32 rows (2 m16 tiles). 8 warps/CTA -> 256-row tiles. No
// __syncthreads in the main loop.
// ---------------------------------------------------------------------------

#define WSTRIDE 72            // halfs per weight row (pad 64->72: conflict-free)
#define WH_OFF  0             // 4*64*72*2 = 36864
#define WL_OFF  36864
#define BI_OFF  73728         // 4*64 f32
#define W4_OFF  74752         // 3*64 f32
#define B4_OFF  75520         // 3 f32
#define SMEM_BYTES 75648

__device__ __forceinline__ void mma16816(float c[4], const uint32_t a[4],
                                         uint32_t b0, uint32_t b1) {
    asm volatile(
        "mma.sync.aligned.m16n8k16.row.col.f32.f16.f16.f32 "
        "{%0,%1,%2,%3},{%4,%5,%6,%7},{%8,%9},{%0,%1,%2,%3};"
        : "+f"(c[0]), "+f"(c[1]), "+f"(c[2]), "+f"(c[3])
        : "r"(a[0]), "r"(a[1]), "r"(a[2]), "r"(a[3]), "r"(b0), "r"(b1));
}

__device__ __forceinline__ uint32_t pack_hi(float v0, float v1) {
    __half2 h = __halves2half2(__float2half_rn(v0), __float2half_rn(v1));
    return *reinterpret_cast<uint32_t*>(&h);
}
__device__ __forceinline__ uint32_t pack_lo(float v0, float v1, uint32_t hi) {
    __half2 h = *reinterpret_cast<__half2*>(&hi);
    float r0 = v0 - __low2float(h);
    float r1 = v1 - __high2float(h);
    __half2 l = __halves2half2(__float2half_rn(r0), __float2half_rn(r1));
    return *reinterpret_cast<uint32_t*>(&l);
}

// One MMA layer: C[mt][nt][4] += 3-pass split product of A (regs) x W^T (SMEM).
template <int KT>
__device__ __forceinline__ void run_layer(float C[2][8][4],
                                          const uint32_t AH[2][4][4],
                                          const uint32_t AL[2][4][4],
                                          const half* __restrict__ whB,
                                          const half* __restrict__ wlB) {
#pragma unroll
    for (int mt = 0; mt < 2; mt++)
#pragma unroll
        for (int nt = 0; nt < 8; nt++)
#pragma unroll
            for (int r = 0; r < 4; r++) C[mt][nt][r] = 0.f;

#pragma unroll
    for (int i = 0; i < 4; i++) {       // nt pair {2i, 2i+1}
#pragma unroll
        for (int kt = 0; kt < KT; kt++) {
            const half* p0 = whB + (2 * i) * (8 * WSTRIDE) + kt * 16;
            const half* p1 = p0 + 8 * WSTRIDE;
            uint32_t bh00 = *(const uint32_t*)(p0);
            uint32_t bh01 = *(const uint32_t*)(p0 + 8);
            uint32_t bh10 = *(const uint32_t*)(p1);
            uint32_t bh11 = *(const uint32_t*)(p1 + 8);
            const half* q0 = wlB + (2 * i) * (8 * WSTRIDE) + kt * 16;
            const half* q1 = q0 + 8 * WSTRIDE;
            uint32_t bl00 = *(const uint32_t*)(q0);
            uint32_t bl01 = *(const uint32_t*)(q0 + 8);
            uint32_t bl10 = *(const uint32_t*)(q1);
            uint32_t bl11 = *(const uint32_t*)(q1 + 8);

            // pass 1: A_hi * W_hi  (4 independent accumulator chains)
            mma16816(C[0][2 * i],     AH[0][kt], bh00, bh01);
            mma16816(C[0][2 * i + 1], AH[0][kt], bh10, bh11);
            mma16816(C[1][2 * i],     AH[1][kt], bh00, bh01);
            mma16816(C[1][2 * i + 1], AH[1][kt], bh10, bh11);
            // pass 2: A_lo * W_hi
            mma16816(C[0][2 * i],     AL[0][kt], bh00, bh01);
            mma16816(C[0][2 * i + 1], AL[0][kt], bh10, bh11);
            mma16816(C[1][2 * i],     AL[1][kt], bh00, bh01);
            mma16816(C[1][2 * i + 1], AL[1][kt], bh10, bh11);
            // pass 3: A_hi * W_lo
            mma16816(C[0][2 * i],     AH[0][kt], bl00, bl01);
            mma16816(C[0][2 * i + 1], AH[0][kt], bl10, bl11);
            mma16816(C[1][2 * i],     AH[1][kt], bl00, bl01);
            mma16816(C[1][2 * i + 1], AH[1][kt], bl10, bl11);
        }
    }
}

__global__ void __launch_bounds__(256)
mlp_hmma_kernel(const float* __restrict__ x,
                const float* __restrict__ W0, const float* __restrict__ b0,
                const float* __restrict__ W1, const float* __restrict__ b1,
                const float* __restrict__ W2, const float* __restrict__ b2,
                const float* __restrict__ W3, const float* __restrict__ b3,
                const float* __restrict__ W4, const float* __restrict__ b4,
                float* __restrict__ out, int n, int ntiles)
{
    extern __shared__ char sm[];
    half*  WH  = (half*)(sm + WH_OFF);
    half*  WL  = (half*)(sm + WL_OFF);
    float* BI  = (float*)(sm + BI_OFF);
    float* W4p = (float*)(sm + W4_OFF);
    float* B4p = (float*)(sm + B4_OFF);

    const int tid  = threadIdx.x;
    const int warp = tid >> 5;
    const int lane = tid & 31;
    const int q    = lane & 3;      // thread-in-group
    const int td4  = lane >> 2;     // group id

    // ---- stage weights: split fp32 -> fp16 hi/lo into padded SMEM ----
    {
        const float* Ws[4] = {W0, W1, W2, W3};
        const float* bs[4] = {b0, b1, b2, b3};
#pragma unroll
        for (int l = 0; l < 4; l++) {
            const int K = (l == 0) ? 32 : 64;
            for (int idx = tid; idx < 64 * K; idx += 256) {
                int nr = idx / K, k = idx - nr * K;
                float v = Ws[l][idx];
                half hh = __float2half_rn(v);
                half hl = __float2half_rn(v - __half2float(hh));
                int o = (l * 64 + nr) * WSTRIDE + k;
                WH[o] = hh;
                WL[o] = hl;
            }
            if (tid < 64) BI[l * 64 + tid] = bs[l][tid];
        }
        if (tid < 192) W4p[tid] = W4[tid];
        if (tid < 3)   B4p[tid] = b4[tid];
    }
    __syncthreads();

    // per-thread B-fragment base: row td4, col offset 2q (halfs)
    const half* whB = WH + td4 * WSTRIDE + 2 * q;
    const half* wlB = WL + td4 * WSTRIDE + 2 * q;

    uint32_t AH[2][4][4], AL[2][4][4];
    float C[2][8][4];

    for (int tile = blockIdx.x; tile < ntiles; tile += gridDim.x) {
        const long rbase = (long)tile * 256 + warp * 32;

        // ---- build layer-0 A fragments straight from global X (K=32 -> 2 kt)
#pragma unroll
        for (int mt = 0; mt < 2; mt++) {
            long r0 = rbase + mt * 16 + td4;
            long r1 = r0 + 8;
            if (r0 > n - 1) r0 = n - 1;
            if (r1 > n - 1) r1 = n - 1;
            const float* x0 = x + r0 * 32 + 2 * q;
            const float* x1 = x + r1 * 32 + 2 * q;
#pragma unroll
            for (int kt = 0; kt < 2; kt++) {
                float2 a = *(const float2*)(x0 + kt * 16);
                float2 b = *(const float2*)(x1 + kt * 16);
                float2 c = *(const float2*)(x0 + kt * 16 + 8);
                float2 d = *(const float2*)(x1 + kt * 16 + 8);
                AH[mt][kt][0] = pack_hi(a.x, a.y);
                AL[mt][kt][0] = pack_lo(a.x, a.y, AH[mt][kt][0]);
                AH[mt][kt][1] = pack_hi(b.x, b.y);
                AL[mt][kt][1] = pack_lo(b.x, b.y, AH[mt][kt][1]);
                AH[mt][kt][2] = pack_hi(c.x, c.y);
                AL[mt][kt][2] = pack_lo(c.x, c.y, AH[mt][kt][2]);
                AH[mt][kt][3] = pack_hi(d.x, d.y);
                AL[mt][kt][3] = pack_lo(d.x, d.y, AH[mt][kt][3]);
            }
        }

        // ---- 4 hidden layers ----
#pragma unroll
        for (int l = 0; l < 4; l++) {
            const half* whL = whB + l * 64 * WSTRIDE;
            const half* wlL = wlB + l * 64 * WSTRIDE;
            if (l == 0) run_layer<2>(C, AH, AL, whL, wlL);
            else        run_layer<4>(C, AH, AL, whL, wlL);

            if (l < 3) {
                // epilogue: bias + ReLU + re-split -> next-layer A fragments.
                // next A ktile i <- D ntiles (2i, 2i+1); pure register repack.
                const float* bl = BI + l * 64 + 2 * q;
#pragma unroll
                for (int i = 0; i < 4; i++) {
#pragma unroll
                    for (int mt = 0; mt < 2; mt++) {
#pragma unroll
                        for (int s = 0; s < 2; s++) {
                            int nt = 2 * i + s;
                            float2 bv = *(const float2*)(bl + nt * 8);
                            float v0 = fmaxf(C[mt][nt][0] + bv.x, 0.f);
                            float v1 = fmaxf(C[mt][nt][1] + bv.y, 0.f);
                            float v2 = fmaxf(C[mt][nt][2] + bv.x, 0.f);
                            float v3 = fmaxf(C[mt][nt][3] + bv.y, 0.f);
                            uint32_t h01 = pack_hi(v0, v1);
                            uint32_t h23 = pack_hi(v2, v3);
                            AH[mt][i][2 * s]     = h01;
                            AH[mt][i][2 * s + 1] = h23;
                            AL[mt][i][2 * s]     = pack_lo(v0, v1, h01);
                            AL[mt][i][2 * s + 1] = pack_lo(v2, v3, h23);
                        }
                    }
                }
            }
        }

        // ---- final: bias3 + ReLU in fp32, then 64->3 + sigmoid ----
        {
            const float* bl = BI + 3 * 64 + 2 * q;
#pragma unroll
            for (int mt = 0; mt < 2; mt++)
#pragma unroll
                for (int nt = 0; nt < 8; nt++) {
                    float2 bv = *(const float2*)(bl + nt * 8);
                    C[mt][nt][0] = fmaxf(C[mt][nt][0] + bv.x, 0.f);
                    C[mt][nt][1] = fmaxf(C[mt][nt][1] + bv.y, 0.f);
                    C[mt][nt][2] = fmaxf(C[mt][nt][2] + bv.x, 0.f);
                    C[mt][nt][3] = fmaxf(C[mt][nt][3] + bv.y, 0.f);
                }

#pragma unroll
            for (int mt = 0; mt < 2; mt++) {
                long r0 = rbase + mt * 16 + td4;
                long r1 = r0 + 8;
#pragma unroll
                for (int p = 0; p < 3; p++) {
                    float a0 = 0.f, a1 = 0.f;
                    const float* wp = W4p + p * 64 + 2 * q;
#pragma unroll
                    for (int j = 0; j < 8; j++) {
                        float2 w = *(const float2*)(wp + j * 8);
                        a0 = fmaf(C[mt][j][0], w.x, a0);
                        a0 = fmaf(C[mt][j][1], w.y, a0);
                        a1 = fmaf(C[mt][j][2], w.x, a1);
                        a1 = fmaf(C[mt][j][3], w.y, a1);
                    }
                    // quad (t%4) butterfly reduction: full sum in all 4 lanes
                    a0 += __shfl_xor_sync(0xFFFFFFFF, a0, 1);
                    a0 += __shfl_xor_sync(0xFFFFFFFF, a0, 2);
                    a1 += __shfl_xor_sync(0xFFFFFFFF, a1, 1);
                    a1 += __shfl_xor_sync(0xFFFFFFFF, a1, 2);
                    float o0 = __fdividef(1.f, 1.f + __expf(-(a0 + B4p[p])));
                    float o1 = __fdividef(1.f, 1.f + __expf(-(a1 + B4p[p])));
                    if (q == p) {
                        if (r0 < n) out[r0 * 3 + p] = o0;
                        if (r1 < n) out[r1 * 3 + p] = o1;
                    }
                }
            }
        }
    }
}

extern "C" void kernel_launch(void* const* d_in, const int* in_sizes, int n_in,
                              void* d_out, int out_size) {
    const float* x  = (const float*)d_in[0];
    const float* W0 = (const float*)d_in[1];
    const float* b0 = (const float*)d_in[2];
    const float* W1 = (const float*)d_in[3];
    const float* b1 = (const float*)d_in[4];
    const float* W2 = (const float*)d_in[5];
    const float* b2 = (const float*)d_in[6];
    const float* W3 = (const float*)d_in[7];
    const float* b3 = (const float*)d_in[8];
    const float* W4 = (const float*)d_in[9];
    const float* b4 = (const float*)d_in[10];
    float* out = (float*)d_out;

    const int n = in_sizes[0] / 32;
    const int ntiles = (n + 255) / 256;

    cudaFuncSetAttribute(mlp_hmma_kernel,
                         cudaFuncAttributeMaxDynamicSharedMemorySize, SMEM_BYTES);

    int blocks = 148 * 2;
    if (ntiles < blocks) blocks = ntiles;

    mlp_hmma_kernel<<<blocks, 256, SMEM_BYTES>>>(
        x, W0, b0, W1, b1, W2, b2, W3, b3, W4, b4, out, n, ntiles);
}

// round 4
// speedup vs baseline: 10.3422x; 1.6101x over previous
#include <cuda_runtime.h>
#include <cuda_fp16.h>
#include <stdint.h>
#include <math.h>

// ---------------------------------------------------------------------------
// Fused 5-layer MLP (32->64->64->64->64->3, ReLU hidden, sigmoid out).
// mma.sync m16n8k16 fp16, ASYMMETRIC split: W = Wh + Wl (exact, 2 passes),
// A rounded to single fp16 (error ~2^-12 -> end-to-end ~2e-4 < 1e-3).
// Activations live in registers across all layers (D-frag == next A-frag).
// Weights pre-shuffled into fragment-ordered SMEM: one uint4 (LDS.128) per
// lane per (layer, n-pair, ktile) per pass -> minimal LDS issue traffic.
// __launch_bounds__(256,2): 2 CTAs/SM, 4 warps/SMSP for latency hiding.
// ---------------------------------------------------------------------------

#define FRAG_HI_OFF 0          // 4l*4i*4kt*32lane*16B = 32768
#define FRAG_LO_OFF 32768
#define BI_OFF      65536      // 4*64 f32 = 1024
#define W4_OFF      66560      // 3*64 f32 = 768
#define B4_OFF      67328      // 3 f32
#define SMEM_BYTES  67456

__device__ __forceinline__ void mma_acc(float c[4], const uint32_t a[4],
                                        uint32_t b0, uint32_t b1) {
    asm volatile(
        "mma.sync.aligned.m16n8k16.row.col.f32.f16.f16.f32 "
        "{%0,%1,%2,%3},{%4,%5,%6,%7},{%8,%9},{%0,%1,%2,%3};"
        : "+f"(c[0]), "+f"(c[1]), "+f"(c[2]), "+f"(c[3])
        : "r"(a[0]), "r"(a[1]), "r"(a[2]), "r"(a[3]), "r"(b0), "r"(b1));
}
// C = A*B (no accumulate) — saves explicit zero-init of C
__device__ __forceinline__ void mma_init(float c[4], const uint32_t a[4],
                                         uint32_t b0, uint32_t b1) {
    const float z = 0.f;
    asm volatile(
        "mma.sync.aligned.m16n8k16.row.col.f32.f16.f16.f32 "
        "{%0,%1,%2,%3},{%4,%5,%6,%7},{%8,%9},{%10,%10,%10,%10};"
        : "=f"(c[0]), "=f"(c[1]), "=f"(c[2]), "=f"(c[3])
        : "r"(a[0]), "r"(a[1]), "r"(a[2]), "r"(a[3]), "r"(b0), "r"(b1), "f"(z));
}

__device__ __forceinline__ uint32_t pack_h2(float v0, float v1) {
    __half2 h = __halves2half2(__float2half_rn(v0), __float2half_rn(v1));
    return *reinterpret_cast<uint32_t*>(&h);
}

// one layer: C = A x (Wh + Wl)^T, fragment-ordered weights
template <int KT>
__device__ __forceinline__ void run_layer(float C[2][8][4],
                                          const uint32_t A[2][4][4],
                                          const uint4* __restrict__ fh,
                                          const uint4* __restrict__ fl,
                                          int lane) {
#pragma unroll
    for (int i = 0; i < 4; i++) {
#pragma unroll
        for (int kt = 0; kt < KT; kt++) {
            uint4 bh = fh[(i * 4 + kt) * 32 + lane];
            uint4 bl = fl[(i * 4 + kt) * 32 + lane];
            if (kt == 0) {
                mma_init(C[0][2 * i],     A[0][0], bh.x, bh.y);
                mma_init(C[0][2 * i + 1], A[0][0], bh.z, bh.w);
                mma_init(C[1][2 * i],     A[1][0], bh.x, bh.y);
                mma_init(C[1][2 * i + 1], A[1][0], bh.z, bh.w);
            } else {
                mma_acc(C[0][2 * i],     A[0][kt], bh.x, bh.y);
                mma_acc(C[0][2 * i + 1], A[0][kt], bh.z, bh.w);
                mma_acc(C[1][2 * i],     A[1][kt], bh.x, bh.y);
                mma_acc(C[1][2 * i + 1], A[1][kt], bh.z, bh.w);
            }
            mma_acc(C[0][2 * i],     A[0][kt], bl.x, bl.y);
            mma_acc(C[0][2 * i + 1], A[0][kt], bl.z, bl.w);
            mma_acc(C[1][2 * i],     A[1][kt], bl.x, bl.y);
            mma_acc(C[1][2 * i + 1], A[1][kt], bl.z, bl.w);
        }
    }
}

__global__ void __launch_bounds__(256, 2)
mlp_hmma2_kernel(const float* __restrict__ x,
                 const float* __restrict__ W0, const float* __restrict__ b0,
                 const float* __restrict__ W1, const float* __restrict__ b1,
                 const float* __restrict__ W2, const float* __restrict__ b2,
                 const float* __restrict__ W3, const float* __restrict__ b3,
                 const float* __restrict__ W4, const float* __restrict__ b4,
                 float* __restrict__ out, int n, int ntiles)
{
    extern __shared__ char sm[];
    uint4* FH  = (uint4*)(sm + FRAG_HI_OFF);
    uint4* FL  = (uint4*)(sm + FRAG_LO_OFF);
    float* BI  = (float*)(sm + BI_OFF);
    float* W4p = (float*)(sm + W4_OFF);
    float* B4p = (float*)(sm + B4_OFF);

    const int tid  = threadIdx.x;
    const int warp = tid >> 5;
    const int lane = tid & 31;
    const int q    = lane & 3;
    const int td4  = lane >> 2;

    // ---- stage weights into fragment order, split fp32 -> fp16 hi+lo ----
    {
        const float* Ws[4] = {W0, W1, W2, W3};
        const float* bs[4] = {b0, b1, b2, b3};
        for (int idx = tid; idx < 4 * 4 * 4 * 32; idx += 256) {
            int ln = idx & 31;
            int kt = (idx >> 5) & 3;
            int i  = (idx >> 7) & 3;
            int l  = idx >> 9;
            int lq = ln & 3, ltd4 = ln >> 2;
            const int K = (l == 0) ? 32 : 64;
            const float* W = Ws[l];
            uint32_t rh[4], rl[4];
#pragma unroll
            for (int r = 0; r < 4; r++) {
                int nn = 8 * (2 * i + (r >> 1)) + ltd4;
                int k  = 16 * kt + 2 * lq + (r & 1) * 8;
                float w0 = (k     < K) ? W[nn * K + k]     : 0.f;
                float w1 = (k + 1 < K) ? W[nn * K + k + 1] : 0.f;
                half h0 = __float2half_rn(w0);
                half h1 = __float2half_rn(w1);
                half l0 = __float2half_rn(w0 - __half2float(h0));
                half l1 = __float2half_rn(w1 - __half2float(h1));
                __half2 ph = __halves2half2(h0, h1);
                __half2 pl = __halves2half2(l0, l1);
                rh[r] = *reinterpret_cast<uint32_t*>(&ph);
                rl[r] = *reinterpret_cast<uint32_t*>(&pl);
            }
            FH[idx] = make_uint4(rh[0], rh[1], rh[2], rh[3]);
            FL[idx] = make_uint4(rl[0], rl[1], rl[2], rl[3]);
        }
        if (tid < 256) {
            int l = tid >> 6, j = tid & 63;
            BI[tid] = ((const float*[4]){b0, b1, b2, b3})[l][j];
        }
        if (tid < 192) W4p[tid] = W4[tid];
        if (tid < 3)   B4p[tid] = b4[tid];
    }
    __syncthreads();

    uint32_t A[2][4][4];
    float C[2][8][4];

    for (int tile = blockIdx.x; tile < ntiles; tile += gridDim.x) {
        const long rbase = (long)tile * 256 + warp * 32;

        // ---- layer-0 A fragments straight from global X (fp16 rounded) ----
#pragma unroll
        for (int mt = 0; mt < 2; mt++) {
            long r0 = rbase + mt * 16 + td4;
            long r1 = r0 + 8;
            if (r0 > n - 1) r0 = n - 1;
            if (r1 > n - 1) r1 = n - 1;
            const float* x0 = x + r0 * 32 + 2 * q;
            const float* x1 = x + r1 * 32 + 2 * q;
#pragma unroll
            for (int kt = 0; kt < 2; kt++) {
                float2 a = *(const float2*)(x0 + kt * 16);
                float2 b = *(const float2*)(x1 + kt * 16);
                float2 c = *(const float2*)(x0 + kt * 16 + 8);
                float2 d = *(const float2*)(x1 + kt * 16 + 8);
                A[mt][kt][0] = pack_h2(a.x, a.y);
                A[mt][kt][1] = pack_h2(b.x, b.y);
                A[mt][kt][2] = pack_h2(c.x, c.y);
                A[mt][kt][3] = pack_h2(d.x, d.y);
            }
        }

        // ---- 4 hidden layers ----
#pragma unroll
        for (int l = 0; l < 4; l++) {
            const uint4* fh = FH + l * 16 * 32;
            const uint4* fl = FL + l * 16 * 32;
            if (l == 0) run_layer<2>(C, A, fh, fl, lane);
            else        run_layer<4>(C, A, fh, fl, lane);

            if (l < 3) {
                // bias + ReLU + fp16 round -> next-layer A frags (reg repack)
                const float* blp = BI + l * 64 + 2 * q;
#pragma unroll
                for (int i = 0; i < 4; i++)
#pragma unroll
                    for (int mt = 0; mt < 2; mt++)
#pragma unroll
                        for (int s = 0; s < 2; s++) {
                            int nt = 2 * i + s;
                            float2 bv = *(const float2*)(blp + nt * 8);
                            float v0 = fmaxf(C[mt][nt][0] + bv.x, 0.f);
                            float v1 = fmaxf(C[mt][nt][1] + bv.y, 0.f);
                            float v2 = fmaxf(C[mt][nt][2] + bv.x, 0.f);
                            float v3 = fmaxf(C[mt][nt][3] + bv.y, 0.f);
                            A[mt][i][2 * s]     = pack_h2(v0, v1);
                            A[mt][i][2 * s + 1] = pack_h2(v2, v3);
                        }
            }
        }

        // ---- final: bias + ReLU (fp32), 64->3 FFMA, sigmoid ----
        {
            const float* blp = BI + 3 * 64 + 2 * q;
#pragma unroll
            for (int mt = 0; mt < 2; mt++)
#pragma unroll
                for (int nt = 0; nt < 8; nt++) {
                    float2 bv = *(const float2*)(blp + nt * 8);
                    C[mt][nt][0] = fmaxf(C[mt][nt][0] + bv.x, 0.f);
                    C[mt][nt][1] = fmaxf(C[mt][nt][1] + bv.y, 0.f);
                    C[mt][nt][2] = fmaxf(C[mt][nt][2] + bv.x, 0.f);
                    C[mt][nt][3] = fmaxf(C[mt][nt][3] + bv.y, 0.f);
                }

#pragma unroll
            for (int mt = 0; mt < 2; mt++) {
                long r0 = rbase + mt * 16 + td4;
                long r1 = r0 + 8;
#pragma unroll
                for (int p = 0; p < 3; p++) {
                    float a0 = 0.f, a1 = 0.f;
                    const float* wp = W4p + p * 64 + 2 * q;
#pragma unroll
                    for (int j = 0; j < 8; j++) {
                        float2 w = *(const float2*)(wp + j * 8);
                        a0 = fmaf(C[mt][j][0], w.x, a0);
                        a0 = fmaf(C[mt][j][1], w.y, a0);
                        a1 = fmaf(C[mt][j][2], w.x, a1);
                        a1 = fmaf(C[mt][j][3], w.y, a1);
                    }
                    a0 += __shfl_xor_sync(0xFFFFFFFF, a0, 1);
                    a0 += __shfl_xor_sync(0xFFFFFFFF, a0, 2);
                    a1 += __shfl_xor_sync(0xFFFFFFFF, a1, 1);
                    a1 += __shfl_xor_sync(0xFFFFFFFF, a1, 2);
                    float o0 = __fdividef(1.f, 1.f + __expf(-(a0 + B4p[p])));
                    float o1 = __fdividef(1.f, 1.f + __expf(-(a1 + B4p[p])));
                    if (q == p) {
                        if (r0 < n) out[r0 * 3 + p] = o0;
                        if (r1 < n) out[r1 * 3 + p] = o1;
                    }
                }
            }
        }
    }
}

extern "C" void kernel_launch(void* const* d_in, const int* in_sizes, int n_in,
                              void* d_out, int out_size) {
    const float* x  = (const float*)d_in[0];
    const float* W0 = (const float*)d_in[1];
    const float* b0 = (const float*)d_in[2];
    const float* W1 = (const float*)d_in[3];
    const float* b1 = (const float*)d_in[4];
    const float* W2 = (const float*)d_in[5];
    const float* b2 = (const float*)d_in[6];
    const float* W3 = (const float*)d_in[7];
    const float* b3 = (const float*)d_in[8];
    const float* W4 = (const float*)d_in[9];
    const float* b4 = (const float*)d_in[10];
    float* out = (float*)d_out;

    const int n = in_sizes[0] / 32;
    const int ntiles = (n + 255) / 256;

    cudaFuncSetAttribute(mlp_hmma2_kernel,
                         cudaFuncAttributeMaxDynamicSharedMemorySize, SMEM_BYTES);

    int blocks = 148 * 2;
    if (ntiles < blocks) blocks = ntiles;

    mlp_hmma2_kernel<<<blocks, 256, SMEM_BYTES>>>(
        x, W0, b0, W1, b1, W2, b2, W3, b3, W4, b4, out, n, ntiles);
}

// round 6
// speedup vs baseline: 14.5629x; 1.4081x over previous
#include <cuda_runtime.h>
#include <cuda_fp16.h>
#include <stdint.h>
#include <math.h>

// ---------------------------------------------------------------------------
// Fused 5-layer MLP (32->64->64->64->64->3, ReLU hidden, sigmoid out).
// mma.sync m16n8k16 pure fp16 (single pass; measured precision headroom is
// ~400x, predicted ~5e-6 rel_err). Activations stay in registers across all
// layers (D-frag == next A-frag ownership). Weights pre-shuffled into
// fragment-ordered SMEM (1 LDS.128 per lane per 4-MMA group). X prefetched
// tile-ahead into double-buffered SMEM via cp.async. 2 CTAs/SM.
// ---------------------------------------------------------------------------

#define FH_OFF     0           // 4l*4i*4kt*32lane*16B = 32768
#define XB_OFF     32768       // 2 bufs * 256 rows * 36 floats * 4B = 73728
#define XB_STRIDE  36          // floats per row (16B-aligned, bank-staggered)
#define XB_BUF_FLOATS (256 * XB_STRIDE)
#define XB_BUF_BYTES  (XB_BUF_FLOATS * 4)
#define BI_OFF     106496      // 4*64 f32 = 1024
#define W4_OFF     107520      // 3*64 f32 = 768
#define B4_OFF     108288      // 3 f32 (+pad)
#define SMEM_BYTES 108304

__device__ __forceinline__ void mma_acc(float c[4], const uint32_t a[4],
                                        uint32_t b0, uint32_t b1) {
    asm volatile(
        "mma.sync.aligned.m16n8k16.row.col.f32.f16.f16.f32 "
        "{%0,%1,%2,%3},{%4,%5,%6,%7},{%8,%9},{%0,%1,%2,%3};"
        : "+f"(c[0]), "+f"(c[1]), "+f"(c[2]), "+f"(c[3])
        : "r"(a[0]), "r"(a[1]), "r"(a[2]), "r"(a[3]), "r"(b0), "r"(b1));
}
__device__ __forceinline__ void mma_init(float c[4], const uint32_t a[4],
                                         uint32_t b0, uint32_t b1) {
    const float z = 0.f;
    asm volatile(
        "mma.sync.aligned.m16n8k16.row.col.f32.f16.f16.f32 "
        "{%0,%1,%2,%3},{%4,%5,%6,%7},{%8,%9},{%10,%10,%10,%10};"
        : "=f"(c[0]), "=f"(c[1]), "=f"(c[2]), "=f"(c[3])
        : "r"(a[0]), "r"(a[1]), "r"(a[2]), "r"(a[3]), "r"(b0), "r"(b1), "f"(z));
}

// packed convert: lo half <- v0, hi half <- v1 (one instruction)
__device__ __forceinline__ uint32_t pack_h2(float v0, float v1) {
    uint32_t r;
    asm("cvt.rn.f16x2.f32 %0, %1, %2;" : "=r"(r) : "f"(v1), "f"(v0));
    return r;
}

// one layer: C = A x Wh^T (kt-outer for 16 independent accumulator chains)
template <int KT>
__device__ __forceinline__ void run_layer(float C[2][8][4],
                                          const uint32_t A[2][4][4],
                                          const uint4* __restrict__ fh,
                                          int lane) {
#pragma unroll
    for (int kt = 0; kt < KT; kt++) {
#pragma unroll
        for (int i = 0; i < 4; i++) {
            uint4 bh = fh[(i * 4 + kt) * 32 + lane];
            if (kt == 0) {
                mma_init(C[0][2 * i],     A[0][0], bh.x, bh.y);
                mma_init(C[0][2 * i + 1], A[0][0], bh.z, bh.w);
                mma_init(C[1][2 * i],     A[1][0], bh.x, bh.y);
                mma_init(C[1][2 * i + 1], A[1][0], bh.z, bh.w);
            } else {
                mma_acc(C[0][2 * i],     A[0][kt], bh.x, bh.y);
                mma_acc(C[0][2 * i + 1], A[0][kt], bh.z, bh.w);
                mma_acc(C[1][2 * i],     A[1][kt], bh.x, bh.y);
                mma_acc(C[1][2 * i + 1], A[1][kt], bh.z, bh.w);
            }
        }
    }
}

__global__ void __launch_bounds__(256, 2)
mlp_hmma3_kernel(const float* __restrict__ x,
                 const float* __restrict__ W0, const float* __restrict__ b0,
                 const float* __restrict__ W1, const float* __restrict__ b1,
                 const float* __restrict__ W2, const float* __restrict__ b2,
                 const float* __restrict__ W3, const float* __restrict__ b3,
                 const float* __restrict__ W4, const float* __restrict__ b4,
                 float* __restrict__ out, int n, int ntiles)
{
    extern __shared__ char sm[];
    uint4* FH  = (uint4*)(sm + FH_OFF);
    float* XB  = (float*)(sm + XB_OFF);
    float* BI  = (float*)(sm + BI_OFF);
    float* W4p = (float*)(sm + W4_OFF);
    float* B4p = (float*)(sm + B4_OFF);

    const int tid  = threadIdx.x;
    const int warp = tid >> 5;
    const int lane = tid & 31;
    const int q    = lane & 3;
    const int td4  = lane >> 2;

    uint32_t xb_u32;
    asm("{ .reg .u64 t; cvta.to.shared.u64 t, %1; cvt.u32.u64 %0, t; }"
        : "=r"(xb_u32) : "l"((const void*)XB));

    // ---- prefetch tile0 X -> buf0 (starts DRAM fetch before staging) ----
    {
        long rb = (long)blockIdx.x * 256;
        for (int c = tid; c < 2048; c += 256) {
            int row = c >> 3, seg = c & 7;
            long gr = rb + row;
            int ok = gr < n;
            const float* g = x + (ok ? gr : (long)(n - 1)) * 32 + seg * 4;
            uint32_t d = xb_u32 + (uint32_t)(row * (XB_STRIDE * 4) + seg * 16);
            int sz = ok ? 16 : 0;
            asm volatile("cp.async.cg.shared.global [%0], [%1], 16, %2;"
                         :: "r"(d), "l"(g), "r"(sz) : "memory");
        }
        asm volatile("cp.async.commit_group;" ::: "memory");
    }

    // ---- stage weights into fragment order (fp16), bias/W4 fp32 ----
    {
        const float* Ws[4] = {W0, W1, W2, W3};
        for (int idx = tid; idx < 4 * 4 * 4 * 32; idx += 256) {
            int ln = idx & 31;
            int kt = (idx >> 5) & 3;
            int i  = (idx >> 7) & 3;
            int l  = idx >> 9;
            int lq = ln & 3, ltd4 = ln >> 2;
            const int K = (l == 0) ? 32 : 64;
            const float* W = Ws[l];
            uint32_t rh[4];
#pragma unroll
            for (int r = 0; r < 4; r++) {
                int nn = 8 * (2 * i + (r >> 1)) + ltd4;
                int k  = 16 * kt + 2 * lq + (r & 1) * 8;
                float w0 = (k     < K) ? W[nn * K + k]     : 0.f;
                float w1 = (k + 1 < K) ? W[nn * K + k + 1] : 0.f;
                rh[r] = pack_h2(w0, w1);
            }
            FH[idx] = make_uint4(rh[0], rh[1], rh[2], rh[3]);
        }
        if (tid < 64)        BI[tid]       = b0[tid];
        else if (tid < 128)  BI[tid]       = b1[tid - 64];
        else if (tid < 192)  BI[tid]       = b2[tid - 128];
        else                 BI[tid]       = b3[tid - 192];
        if (tid < 192) W4p[tid] = W4[tid];
        if (tid < 3)   B4p[tid] = b4[tid];
    }

    uint32_t A[2][4][4];
    float C[2][8][4];

    int it = 0;
    for (int tile = blockIdx.x; tile < ntiles; tile += gridDim.x, it++) {
        const int cur = it & 1;

        // ---- prefetch next tile -> other buffer (or empty group) ----
        {
            int nt_tile = tile + gridDim.x;
            if (nt_tile < ntiles) {
                long rb = (long)nt_tile * 256;
                uint32_t bb = xb_u32 + (uint32_t)((cur ^ 1) * XB_BUF_BYTES);
                for (int c = tid; c < 2048; c += 256) {
                    int row = c >> 3, seg = c & 7;
                    long gr = rb + row;
                    int ok = gr < n;
                    const float* g = x + (ok ? gr : (long)(n - 1)) * 32 + seg * 4;
                    uint32_t d = bb + (uint32_t)(row * (XB_STRIDE * 4) + seg * 16);
                    int sz = ok ? 16 : 0;
                    asm volatile("cp.async.cg.shared.global [%0], [%1], 16, %2;"
                                 :: "r"(d), "l"(g), "r"(sz) : "memory");
                }
            }
            asm volatile("cp.async.commit_group;" ::: "memory");
        }
        // wait for CUR tile's group (older of the <=2 outstanding)
        asm volatile("cp.async.wait_group 1;" ::: "memory");
        __syncthreads();

        // ---- build layer-0 A fragments from SMEM X ----
        {
            const float* xb = XB + cur * XB_BUF_FLOATS;
#pragma unroll
            for (int mt = 0; mt < 2; mt++) {
                int rr = warp * 32 + mt * 16 + td4;
                const float* p0 = xb + rr * XB_STRIDE + 2 * q;
                const float* p1 = p0 + 8 * XB_STRIDE;
#pragma unroll
                for (int kt = 0; kt < 2; kt++) {
                    float2 a = *(const float2*)(p0 + kt * 16);
                    float2 b = *(const float2*)(p1 + kt * 16);
                    float2 c = *(const float2*)(p0 + kt * 16 + 8);
                    float2 d = *(const float2*)(p1 + kt * 16 + 8);
                    A[mt][kt][0] = pack_h2(a.x, a.y);
                    A[mt][kt][1] = pack_h2(b.x, b.y);
                    A[mt][kt][2] = pack_h2(c.x, c.y);
                    A[mt][kt][3] = pack_h2(d.x, d.y);
                }
            }
        }
        __syncthreads();   // protects buffer reuse (readers done before next write)

        // ---- 4 hidden layers ----
#pragma unroll
        for (int l = 0; l < 4; l++) {
            const uint4* fh = FH + l * 16 * 32;
            if (l == 0) run_layer<2>(C, A, fh, lane);
            else        run_layer<4>(C, A, fh, lane);

            if (l < 3) {
                const float* blp = BI + l * 64 + 2 * q;
#pragma unroll
                for (int i = 0; i < 4; i++)
#pragma unroll
                    for (int mt = 0; mt < 2; mt++)
#pragma unroll
                        for (int s = 0; s < 2; s++) {
                            int nt = 2 * i + s;
                            float2 bv = *(const float2*)(blp + nt * 8);
                            float v0 = fmaxf(C[mt][nt][0] + bv.x, 0.f);
                            float v1 = fmaxf(C[mt][nt][1] + bv.y, 0.f);
                            float v2 = fmaxf(C[mt][nt][2] + bv.x, 0.f);
                            float v3 = fmaxf(C[mt][nt][3] + bv.y, 0.f);
                            A[mt][i][2 * s]     = pack_h2(v0, v1);
                            A[mt][i][2 * s + 1] = pack_h2(v2, v3);
                        }
            }
        }

        // ---- final: bias + ReLU (fp32), 64->3 FFMA, sigmoid, store ----
        {
            const float* blp = BI + 3 * 64 + 2 * q;
#pragma unroll
            for (int mt = 0; mt < 2; mt++)
#pragma unroll
                for (int nt = 0; nt < 8; nt++) {
                    float2 bv = *(const float2*)(blp + nt * 8);
                    C[mt][nt][0] = fmaxf(C[mt][nt][0] + bv.x, 0.f);
                    C[mt][nt][1] = fmaxf(C[mt][nt][1] + bv.y, 0.f);
                    C[mt][nt][2] = fmaxf(C[mt][nt][2] + bv.x, 0.f);
                    C[mt][nt][3] = fmaxf(C[mt][nt][3] + bv.y, 0.f);
                }

            const long rbase = (long)tile * 256 + warp * 32;
#pragma unroll
            for (int mt = 0; mt < 2; mt++) {
                long r0 = rbase + mt * 16 + td4;
                long r1 = r0 + 8;
#pragma unroll
                for (int p = 0; p < 3; p++) {
                    float a0 = 0.f, a1 = 0.f;
                    const float* wp = W4p + p * 64 + 2 * q;
#pragma unroll
                    for (int j = 0; j < 8; j++) {
                        float2 w = *(const float2*)(wp + j * 8);
                        a0 = fmaf(C[mt][j][0], w.x, a0);
                        a0 = fmaf(C[mt][j][1], w.y, a0);
                        a1 = fmaf(C[mt][j][2], w.x, a1);
                        a1 = fmaf(C[mt][j][3], w.y, a1);
                    }
                    a0 += __shfl_xor_sync(0xFFFFFFFF, a0, 1);
                    a0 += __shfl_xor_sync(0xFFFFFFFF, a0, 2);
                    a1 += __shfl_xor_sync(0xFFFFFFFF, a1, 1);
                    a1 += __shfl_xor_sync(0xFFFFFFFF, a1, 2);
                    float o0 = __fdividef(1.f, 1.f + __expf(-(a0 + B4p[p])));
                    float o1 = __fdividef(1.f, 1.f + __expf(-(a1 + B4p[p])));
                    if (q == p) {
                        if (r0 < n) out[r0 * 3 + p] = o0;
                        if (r1 < n) out[r1 * 3 + p] = o1;
                    }
                }
            }
        }
    }
}

extern "C" void kernel_launch(void* const* d_in, const int* in_sizes, int n_in,
                              void* d_out, int out_size) {
    const float* x  = (const float*)d_in[0];
    const float* W0 = (const float*)d_in[1];
    const float* b0 = (const float*)d_in[2];
    const float* W1 = (const float*)d_in[3];
    const float* b1 = (const float*)d_in[4];
    const float* W2 = (const float*)d_in[5];
    const float* b2 = (const float*)d_in[6];
    const float* W3 = (const float*)d_in[7];
    const float* b3 = (const float*)d_in[8];
    const float* W4 = (const float*)d_in[9];
    const float* b4 = (const float*)d_in[10];
    float* out = (float*)d_out;

    const int n = in_sizes[0] / 32;
    const int ntiles = (n + 255) / 256;

    cudaFuncSetAttribute(mlp_hmma3_kernel,
                         cudaFuncAttributeMaxDynamicSharedMemorySize, SMEM_BYTES);

    int blocks = 148 * 2;
    if (ntiles < blocks) blocks = ntiles;

    mlp_hmma3_kernel<<<blocks, 256, SMEM_BYTES>>>(
        x, W0, b0, W1, b1, W2, b2, W3, b3, W4, b4, out, n, ntiles);
}

// round 8
// speedup vs baseline: 16.6900x; 1.1461x over previous
#include <cuda_runtime.h>
#include <cuda_fp16.h>
#include <stdint.h>
#include <math.h>

// ---------------------------------------------------------------------------
// Fused 5-layer MLP (32->64->64->64->64->3, ReLU hidden, sigmoid out).
// mma.sync m16n8k16 pure fp16 weights/activations, fp32 accum.
// - Activations stay in registers across ALL layers (D-frag == next A-frag).
// - Per-layer epilogue in packed fp16x2 (cvt -> HADD2 bias -> HMAX2 relu).
// - Final 64->3 layer also done as MMA (n padded to 8), sigmoid + store tail.
// - Weights fragment-ordered in SMEM (LDS.128); X double-buffered cp.async.
// ---------------------------------------------------------------------------

#define FH_OFF     0           // 4l*4i*4kt*32lane*16B = 32768
#define XB_OFF     32768       // 2 bufs * 256 rows * 36 floats * 4B = 73728
#define XB_STRIDE  36
#define XB_BUF_FLOATS (256 * XB_STRIDE)
#define XB_BUF_BYTES  (XB_BUF_FLOATS * 4)
#define FH4_OFF    106496      // final W4 frags: 2*32*16B = 1024
#define BIH_OFF    107520      // bias half2: 4*32*4B = 512
#define B4P_OFF    108032      // 8 f32 (3 + pad)
#define SMEM_BYTES 108064

__device__ __forceinline__ void mma_acc(float c[4], const uint32_t a[4],
                                        uint32_t b0, uint32_t b1) {
    asm volatile(
        "mma.sync.aligned.m16n8k16.row.col.f32.f16.f16.f32 "
        "{%0,%1,%2,%3},{%4,%5,%6,%7},{%8,%9},{%0,%1,%2,%3};"
        : "+f"(c[0]), "+f"(c[1]), "+f"(c[2]), "+f"(c[3])
        : "r"(a[0]), "r"(a[1]), "r"(a[2]), "r"(a[3]), "r"(b0), "r"(b1));
}
__device__ __forceinline__ void mma_init(float c[4], const uint32_t a[4],
                                         uint32_t b0, uint32_t b1) {
    const float z = 0.f;
    asm volatile(
        "mma.sync.aligned.m16n8k16.row.col.f32.f16.f16.f32 "
        "{%0,%1,%2,%3},{%4,%5,%6,%7},{%8,%9},{%10,%10,%10,%10};"
        : "=f"(c[0]), "=f"(c[1]), "=f"(c[2]), "=f"(c[3])
        : "r"(a[0]), "r"(a[1]), "r"(a[2]), "r"(a[3]), "r"(b0), "r"(b1), "f"(z));
}

__device__ __forceinline__ uint32_t pack_h2(float v0, float v1) {
    uint32_t r;
    asm("cvt.rn.f16x2.f32 %0, %1, %2;" : "=r"(r) : "f"(v1), "f"(v0));
    return r;
}
__device__ __forceinline__ uint32_t h2_bias_relu(uint32_t h, uint32_t b) {
    __half2 v = __hmax2(__hadd2(*(__half2*)&h, *(__half2*)&b),
                        __float2half2_rn(0.f));
    return *(uint32_t*)&v;
}

// one hidden layer: C = A x Wh^T
template <int KT>
__device__ __forceinline__ void run_layer(float C[2][8][4],
                                          const uint32_t A[2][4][4],
                                          const uint4* __restrict__ fh,
                                          int lane) {
#pragma unroll
    for (int kt = 0; kt < KT; kt++) {
#pragma unroll
        for (int i = 0; i < 4; i++) {
            uint4 bh = fh[(i * 4 + kt) * 32 + lane];
            if (kt == 0) {
                mma_init(C[0][2 * i],     A[0][0], bh.x, bh.y);
                mma_init(C[0][2 * i + 1], A[0][0], bh.z, bh.w);
                mma_init(C[1][2 * i],     A[1][0], bh.x, bh.y);
                mma_init(C[1][2 * i + 1], A[1][0], bh.z, bh.w);
            } else {
                mma_acc(C[0][2 * i],     A[0][kt], bh.x, bh.y);
                mma_acc(C[0][2 * i + 1], A[0][kt], bh.z, bh.w);
                mma_acc(C[1][2 * i],     A[1][kt], bh.x, bh.y);
                mma_acc(C[1][2 * i + 1], A[1][kt], bh.z, bh.w);
            }
        }
    }
}

__global__ void __launch_bounds__(256, 2)
mlp_hmma4_kernel(const float* __restrict__ x,
                 const float* __restrict__ W0, const float* __restrict__ b0,
                 const float* __restrict__ W1, const float* __restrict__ b1,
                 const float* __restrict__ W2, const float* __restrict__ b2,
                 const float* __restrict__ W3, const float* __restrict__ b3,
                 const float* __restrict__ W4, const float* __restrict__ b4,
                 float* __restrict__ out, int n, int ntiles)
{
    extern __shared__ char sm[];
    uint4*    FH  = (uint4*)(sm + FH_OFF);
    float*    XB  = (float*)(sm + XB_OFF);
    uint4*    FH4 = (uint4*)(sm + FH4_OFF);
    uint32_t* BIH = (uint32_t*)(sm + BIH_OFF);
    float*    B4p = (float*)(sm + B4P_OFF);

    const int tid  = threadIdx.x;
    const int warp = tid >> 5;
    const int lane = tid & 31;
    const int q    = lane & 3;
    const int td4  = lane >> 2;

    uint32_t xb_u32;
    asm("{ .reg .u64 t; cvta.to.shared.u64 t, %1; cvt.u32.u64 %0, t; }"
        : "=r"(xb_u32) : "l"((const void*)XB));

    // ---- prefetch tile0 X -> buf0 ----
    {
        long rb = (long)blockIdx.x * 256;
        for (int c = tid; c < 2048; c += 256) {
            int row = c >> 3, seg = c & 7;
            long gr = rb + row;
            int ok = gr < n;
            const float* g = x + (ok ? gr : (long)(n - 1)) * 32 + seg * 4;
            uint32_t d = xb_u32 + (uint32_t)(row * (XB_STRIDE * 4) + seg * 16);
            int sz = ok ? 16 : 0;
            asm volatile("cp.async.cg.shared.global [%0], [%1], 16, %2;"
                         :: "r"(d), "l"(g), "r"(sz) : "memory");
        }
        asm volatile("cp.async.commit_group;" ::: "memory");
    }

    // ---- stage hidden weights into fragment order (fp16) ----
    {
        const float* Ws[4] = {W0, W1, W2, W3};
        for (int idx = tid; idx < 4 * 4 * 4 * 32; idx += 256) {
            int ln = idx & 31;
            int kt = (idx >> 5) & 3;
            int i  = (idx >> 7) & 3;
            int l  = idx >> 9;
            int lq = ln & 3, ltd4 = ln >> 2;
            const int K = (l == 0) ? 32 : 64;
            const float* W = Ws[l];
            uint32_t rh[4];
#pragma unroll
            for (int r = 0; r < 4; r++) {
                int nn = 8 * (2 * i + (r >> 1)) + ltd4;
                int k  = 16 * kt + 2 * lq + (r & 1) * 8;
                float w0 = (k     < K) ? W[nn * K + k]     : 0.f;
                float w1 = (k + 1 < K) ? W[nn * K + k + 1] : 0.f;
                rh[r] = pack_h2(w0, w1);
            }
            FH[idx] = make_uint4(rh[0], rh[1], rh[2], rh[3]);
        }
        // final-layer W4 frags (n padded 3->8): uint4 = {kt0.b0,kt0.b1,kt1.b0,kt1.b1}
        if (tid < 64) {
            int ktp = tid >> 5, ln = tid & 31;
            int lq = ln & 3, ltd4 = ln >> 2;
            uint32_t rh[4];
#pragma unroll
            for (int r = 0; r < 4; r++) {
                int kt = 2 * ktp + (r >> 1);
                int k  = 16 * kt + 2 * lq + (r & 1) * 8;
                float w0 = (ltd4 < 3) ? W4[ltd4 * 64 + k]     : 0.f;
                float w1 = (ltd4 < 3) ? W4[ltd4 * 64 + k + 1] : 0.f;
                rh[r] = pack_h2(w0, w1);
            }
            FH4[tid] = make_uint4(rh[0], rh[1], rh[2], rh[3]);
        }
        // bias as half2, keyed (layer, nt, q)
        if (tid < 128) {
            int l = tid >> 5, idx = tid & 31;
            int nt = idx >> 2, bq = idx & 3;
            const float* bl = (l == 0) ? b0 : (l == 1) ? b1 : (l == 2) ? b2 : b3;
            BIH[tid] = pack_h2(bl[8 * nt + 2 * bq], bl[8 * nt + 2 * bq + 1]);
        }
        if (tid < 8) B4p[tid] = (tid < 3) ? b4[tid] : 0.f;
    }

    uint32_t A[2][4][4];
    float C[2][8][4];

    int it = 0;
    for (int tile = blockIdx.x; tile < ntiles; tile += gridDim.x, it++) {
        const int cur = it & 1;

        // ---- prefetch next tile -> other buffer ----
        {
            int nt_tile = tile + gridDim.x;
            if (nt_tile < ntiles) {
                long rb = (long)nt_tile * 256;
                uint32_t bb = xb_u32 + (uint32_t)((cur ^ 1) * XB_BUF_BYTES);
                for (int c = tid; c < 2048; c += 256) {
                    int row = c >> 3, seg = c & 7;
                    long gr = rb + row;
                    int ok = gr < n;
                    const float* g = x + (ok ? gr : (long)(n - 1)) * 32 + seg * 4;
                    uint32_t d = bb + (uint32_t)(row * (XB_STRIDE * 4) + seg * 16);
                    int sz = ok ? 16 : 0;
                    asm volatile("cp.async.cg.shared.global [%0], [%1], 16, %2;"
                                 :: "r"(d), "l"(g), "r"(sz) : "memory");
                }
            }
            asm volatile("cp.async.commit_group;" ::: "memory");
        }
        asm volatile("cp.async.wait_group 1;" ::: "memory");
        __syncthreads();

        // ---- layer-0 A fragments from SMEM X ----
        {
            const float* xb = XB + cur * XB_BUF_FLOATS;
#pragma unroll
            for (int mt = 0; mt < 2; mt++) {
                int rr = warp * 32 + mt * 16 + td4;
                const float* p0 = xb + rr * XB_STRIDE + 2 * q;
                const float* p1 = p0 + 8 * XB_STRIDE;
#pragma unroll
                for (int kt = 0; kt < 2; kt++) {
                    float2 a = *(const float2*)(p0 + kt * 16);
                    float2 b = *(const float2*)(p1 + kt * 16);
                    float2 c = *(const float2*)(p0 + kt * 16 + 8);
                    float2 d = *(const float2*)(p1 + kt * 16 + 8);
                    A[mt][kt][0] = pack_h2(a.x, a.y);
                    A[mt][kt][1] = pack_h2(b.x, b.y);
                    A[mt][kt][2] = pack_h2(c.x, c.y);
                    A[mt][kt][3] = pack_h2(d.x, d.y);
                }
            }
        }
        __syncthreads();   // buffer-reuse safety

        // ---- 4 hidden layers, fp16x2 epilogue (incl. l=3 -> A for final) ----
#pragma unroll
        for (int l = 0; l < 4; l++) {
            const uint4* fh = FH + l * 16 * 32;
            if (l == 0) run_layer<2>(C, A, fh, lane);
            else        run_layer<4>(C, A, fh, lane);

            const uint32_t* bih = BIH + l * 32 + q;
#pragma unroll
            for (int i = 0; i < 4; i++) {
                uint32_t b20 = bih[(2 * i) * 4];
                uint32_t b21 = bih[(2 * i + 1) * 4];
#pragma unroll
                for (int mt = 0; mt < 2; mt++) {
                    uint32_t h0 = pack_h2(C[mt][2 * i][0],     C[mt][2 * i][1]);
                    uint32_t h1 = pack_h2(C[mt][2 * i][2],     C[mt][2 * i][3]);
                    uint32_t h2 = pack_h2(C[mt][2 * i + 1][0], C[mt][2 * i + 1][1]);
                    uint32_t h3 = pack_h2(C[mt][2 * i + 1][2], C[mt][2 * i + 1][3]);
                    A[mt][i][0] = h2_bias_relu(h0, b20);
                    A[mt][i][1] = h2_bias_relu(h1, b20);
                    A[mt][i][2] = h2_bias_relu(h2, b21);
                    A[mt][i][3] = h2_bias_relu(h3, b21);
                }
            }
        }

        // ---- final 64->3 as MMA (n padded to 8) + sigmoid + store ----
        {
            uint4 f0 = FH4[lane];
            uint4 f1 = FH4[32 + lane];
            float D0[4], D1[4];
            mma_init(D0, A[0][0], f0.x, f0.y);
            mma_init(D1, A[1][0], f0.x, f0.y);
            mma_acc(D0, A[0][1], f0.z, f0.w);
            mma_acc(D1, A[1][1], f0.z, f0.w);
            mma_acc(D0, A[0][2], f1.x, f1.y);
            mma_acc(D1, A[1][2], f1.x, f1.y);
            mma_acc(D0, A[0][3], f1.z, f1.w);
            mma_acc(D1, A[1][3], f1.z, f1.w);

            const float bc0 = B4p[2 * q];
            const float bc1 = B4p[2 * q + 1];
            const long rbase = (long)tile * 256 + warp * 32;
#pragma unroll
            for (int mt = 0; mt < 2; mt++) {
                const float* Dp = (mt == 0) ? D0 : D1;
                long r0 = rbase + mt * 16 + td4;
                long r1 = r0 + 8;
                float o0 = __fdividef(1.f, 1.f + __expf(-(Dp[0] + bc0)));
                float o1 = __fdividef(1.f, 1.f + __expf(-(Dp[1] + bc1)));
                float o2 = __fdividef(1.f, 1.f + __expf(-(Dp[2] + bc0)));
                float o3 = __fdividef(1.f, 1.f + __expf(-(Dp[3] + bc1)));
                if (q == 0) {
                    if (r0 < n) { out[r0 * 3 + 0] = o0; out[r0 * 3 + 1] = o1; }
                    if (r1 < n) { out[r1 * 3 + 0] = o2; out[r1 * 3 + 1] = o3; }
                } else if (q == 1) {
                    if (r0 < n) out[r0 * 3 + 2] = o0;
                    if (r1 < n) out[r1 * 3 + 2] = o2;
                }
            }
        }
    }
}

extern "C" void kernel_launch(void* const* d_in, const int* in_sizes, int n_in,
                              void* d_out, int out_size) {
    const float* x  = (const float*)d_in[0];
    const float* W0 = (const float*)d_in[1];
    const float* b0 = (const float*)d_in[2];
    const float* W1 = (const float*)d_in[3];
    const float* b1 = (const float*)d_in[4];
    const float* W2 = (const float*)d_in[5];
    const float* b2 = (const float*)d_in[6];
    const float* W3 = (const float*)d_in[7];
    const float* b3 = (const float*)d_in[8];
    const float* W4 = (const float*)d_in[9];
    const float* b4 = (const float*)d_in[10];
    float* out = (float*)d_out;

    const int n = in_sizes[0] / 32;
    const int ntiles = (n + 255) / 256;

    cudaFuncSetAttribute(mlp_hmma4_kernel,
                         cudaFuncAttributeMaxDynamicSharedMemorySize, SMEM_BYTES);

    int blocks = 148 * 2;
    if (ntiles < blocks) blocks = ntiles;

    mlp_hmma4_kernel<<<blocks, 256, SMEM_BYTES>>>(
        x, W0, b0, W1, b1, W2, b2, W3, b3, W4, b4, out, n, ntiles);
}

// round 11
// speedup vs baseline: 18.0379x; 1.0808x over previous
#include <cuda_runtime.h>
#include <cuda_fp16.h>
#include <stdint.h>
#include <math.h>

// ---------------------------------------------------------------------------
// Fused 5-layer MLP (32->64->64->64->64->3, ReLU hidden, sigmoid out).
// Hidden layers: mma.sync m16n8k16 fp16 in / FP16 ACCUM. The fp16 D-fragment
// is bit-identical to the next layer's A-fragment, so inter-layer epilogue is
// just HADD2 bias + HMAX2 relu on packed regs (zero cvt).
// Final 64->3 layer: fp32-accum MMA (precision-critical logits) + sigmoid.
// Weights fragment-ordered in SMEM (LDS.128); X double-buffered cp.async.
// ---------------------------------------------------------------------------

#define FH_OFF     0           // 4l*4i*4kt*32lane*16B = 32768
#define XB_OFF     32768       // 2 bufs * 256 rows * 36 floats * 4B = 73728
#define XB_STRIDE  36
#define XB_BUF_FLOATS (256 * XB_STRIDE)
#define XB_BUF_BYTES  (XB_BUF_FLOATS * 4)
#define FH4_OFF    106496      // final W4 frags: 2*32*16B = 1024
#define BIH_OFF    107520      // bias half2: 4*32*4B = 512
#define B4P_OFF    108032      // 8 f32 (3 + pad)
#define SMEM_BYTES 108064

// fp16-accum MMA: D,C are 2 packed half2 regs
__device__ __forceinline__ void mma_h_acc(uint32_t c[2], const uint32_t a[4],
                                          uint32_t b0, uint32_t b1) {
    asm volatile(
        "mma.sync.aligned.m16n8k16.row.col.f16.f16.f16.f16 "
        "{%0,%1},{%2,%3,%4,%5},{%6,%7},{%0,%1};"
        : "+r"(c[0]), "+r"(c[1])
        : "r"(a[0]), "r"(a[1]), "r"(a[2]), "r"(a[3]), "r"(b0), "r"(b1));
}
__device__ __forceinline__ void mma_h_init(uint32_t c[2], const uint32_t a[4],
                                           uint32_t b0, uint32_t b1) {
    const uint32_t z = 0;
    asm volatile(
        "mma.sync.aligned.m16n8k16.row.col.f16.f16.f16.f16 "
        "{%0,%1},{%2,%3,%4,%5},{%6,%7},{%8,%8};"
        : "=r"(c[0]), "=r"(c[1])
        : "r"(a[0]), "r"(a[1]), "r"(a[2]), "r"(a[3]), "r"(b0), "r"(b1), "r"(z));
}
// fp32-accum MMA (final layer only)
__device__ __forceinline__ void mma_f_acc(float c[4], const uint32_t a[4],
                                          uint32_t b0, uint32_t b1) {
    asm volatile(
        "mma.sync.aligned.m16n8k16.row.col.f32.f16.f16.f32 "
        "{%0,%1,%2,%3},{%4,%5,%6,%7},{%8,%9},{%0,%1,%2,%3};"
        : "+f"(c[0]), "+f"(c[1]), "+f"(c[2]), "+f"(c[3])
        : "r"(a[0]), "r"(a[1]), "r"(a[2]), "r"(a[3]), "r"(b0), "r"(b1));
}
__device__ __forceinline__ void mma_f_init(float c[4], const uint32_t a[4],
                                           uint32_t b0, uint32_t b1) {
    const float z = 0.f;
    asm volatile(
        "mma.sync.aligned.m16n8k16.row.col.f32.f16.f16.f32 "
        "{%0,%1,%2,%3},{%4,%5,%6,%7},{%8,%9},{%10,%10,%10,%10};"
        : "=f"(c[0]), "=f"(c[1]), "=f"(c[2]), "=f"(c[3])
        : "r"(a[0]), "r"(a[1]), "r"(a[2]), "r"(a[3]), "r"(b0), "r"(b1), "f"(z));
}

__device__ __forceinline__ uint32_t pack_h2(float v0, float v1) {
    uint32_t r;
    asm("cvt.rn.f16x2.f32 %0, %1, %2;" : "=r"(r) : "f"(v1), "f"(v0));
    return r;
}
__device__ __forceinline__ uint32_t h2_bias_relu(uint32_t h, uint32_t b) {
    __half2 v = __hmax2(__hadd2(*(__half2*)&h, *(__half2*)&b),
                        __float2half2_rn(0.f));
    return *(uint32_t*)&v;
}

// one hidden layer: C = A x Wh^T (fp16 accum)
template <int KT>
__device__ __forceinline__ void run_layer(uint32_t C[2][8][2],
                                          const uint32_t A[2][4][4],
                                          const uint4* __restrict__ fh,
                                          int lane) {
#pragma unroll
    for (int kt = 0; kt < KT; kt++) {
#pragma unroll
        for (int i = 0; i < 4; i++) {
            uint4 bh = fh[(i * 4 + kt) * 32 + lane];
            if (kt == 0) {
                mma_h_init(C[0][2 * i],     A[0][0], bh.x, bh.y);
                mma_h_init(C[0][2 * i + 1], A[0][0], bh.z, bh.w);
                mma_h_init(C[1][2 * i],     A[1][0], bh.x, bh.y);
                mma_h_init(C[1][2 * i + 1], A[1][0], bh.z, bh.w);
            } else {
                mma_h_acc(C[0][2 * i],     A[0][kt], bh.x, bh.y);
                mma_h_acc(C[0][2 * i + 1], A[0][kt], bh.z, bh.w);
                mma_h_acc(C[1][2 * i],     A[1][kt], bh.x, bh.y);
                mma_h_acc(C[1][2 * i + 1], A[1][kt], bh.z, bh.w);
            }
        }
    }
}

__global__ void __launch_bounds__(256, 2)
mlp_hmma5_kernel(const float* __restrict__ x,
                 const float* __restrict__ W0, const float* __restrict__ b0,
                 const float* __restrict__ W1, const float* __restrict__ b1,
                 const float* __restrict__ W2, const float* __restrict__ b2,
                 const float* __restrict__ W3, const float* __restrict__ b3,
                 const float* __restrict__ W4, const float* __restrict__ b4,
                 float* __restrict__ out, int n, int ntiles)
{
    extern __shared__ char sm[];
    uint4*    FH  = (uint4*)(sm + FH_OFF);
    float*    XB  = (float*)(sm + XB_OFF);
    uint4*    FH4 = (uint4*)(sm + FH4_OFF);
    uint32_t* BIH = (uint32_t*)(sm + BIH_OFF);
    float*    B4p = (float*)(sm + B4P_OFF);

    const int tid  = threadIdx.x;
    const int warp = tid >> 5;
    const int lane = tid & 31;
    const int q    = lane & 3;
    const int td4  = lane >> 2;

    uint32_t xb_u32;
    asm("{ .reg .u64 t; cvta.to.shared.u64 t, %1; cvt.u32.u64 %0, t; }"
        : "=r"(xb_u32) : "l"((const void*)XB));

    // ---- prefetch tile0 X -> buf0 ----
    {
        long rb = (long)blockIdx.x * 256;
        for (int c = tid; c < 2048; c += 256) {
            int row = c >> 3, seg = c & 7;
            long gr = rb + row;
            int ok = gr < n;
            const float* g = x + (ok ? gr : (long)(n - 1)) * 32 + seg * 4;
            uint32_t d = xb_u32 + (uint32_t)(row * (XB_STRIDE * 4) + seg * 16);
            int sz = ok ? 16 : 0;
            asm volatile("cp.async.cg.shared.global [%0], [%1], 16, %2;"
                         :: "r"(d), "l"(g), "r"(sz) : "memory");
        }
        asm volatile("cp.async.commit_group;" ::: "memory");
    }

    // ---- stage hidden weights into fragment order (fp16) ----
    {
        const float* Ws[4] = {W0, W1, W2, W3};
        for (int idx = tid; idx < 4 * 4 * 4 * 32; idx += 256) {
            int ln = idx & 31;
            int kt = (idx >> 5) & 3;
            int i  = (idx >> 7) & 3;
            int l  = idx >> 9;
            int lq = ln & 3, ltd4 = ln >> 2;
            const int K = (l == 0) ? 32 : 64;
            const float* W = Ws[l];
            uint32_t rh[4];
#pragma unroll
            for (int r = 0; r < 4; r++) {
                int nn = 8 * (2 * i + (r >> 1)) + ltd4;
                int k  = 16 * kt + 2 * lq + (r & 1) * 8;
                float w0 = (k     < K) ? W[nn * K + k]     : 0.f;
                float w1 = (k + 1 < K) ? W[nn * K + k + 1] : 0.f;
                rh[r] = pack_h2(w0, w1);
            }
            FH[idx] = make_uint4(rh[0], rh[1], rh[2], rh[3]);
        }
        // final-layer W4 frags (n padded 3->8)
        if (tid < 64) {
            int ktp = tid >> 5, ln = tid & 31;
            int lq = ln & 3, ltd4 = ln >> 2;
            uint32_t rh[4];
#pragma unroll
            for (int r = 0; r < 4; r++) {
                int kt = 2 * ktp + (r >> 1);
                int k  = 16 * kt + 2 * lq + (r & 1) * 8;
                float w0 = (ltd4 < 3) ? W4[ltd4 * 64 + k]     : 0.f;
                float w1 = (ltd4 < 3) ? W4[ltd4 * 64 + k + 1] : 0.f;
                rh[r] = pack_h2(w0, w1);
            }
            FH4[tid] = make_uint4(rh[0], rh[1], rh[2], rh[3]);
        }
        // bias as half2, keyed (layer, nt, q)
        if (tid < 128) {
            int l = tid >> 5, idx = tid & 31;
            int nt = idx >> 2, bq = idx & 3;
            const float* bl = (l == 0) ? b0 : (l == 1) ? b1 : (l == 2) ? b2 : b3;
            BIH[tid] = pack_h2(bl[8 * nt + 2 * bq], bl[8 * nt + 2 * bq + 1]);
        }
        if (tid < 8) B4p[tid] = (tid < 3) ? b4[tid] : 0.f;
    }

    uint32_t A[2][4][4];
    uint32_t C[2][8][2];

    int it = 0;
    for (int tile = blockIdx.x; tile < ntiles; tile += gridDim.x, it++) {
        const int cur = it & 1;

        // ---- prefetch next tile -> other buffer ----
        {
            int nt_tile = tile + gridDim.x;
            if (nt_tile < ntiles) {
                long rb = (long)nt_tile * 256;
                uint32_t bb = xb_u32 + (uint32_t)((cur ^ 1) * XB_BUF_BYTES);
                for (int c = tid; c < 2048; c += 256) {
                    int row = c >> 3, seg = c & 7;
                    long gr = rb + row;
                    int ok = gr < n;
                    const float* g = x + (ok ? gr : (long)(n - 1)) * 32 + seg * 4;
                    uint32_t d = bb + (uint32_t)(row * (XB_STRIDE * 4) + seg * 16);
                    int sz = ok ? 16 : 0;
                    asm volatile("cp.async.cg.shared.global [%0], [%1], 16, %2;"
                                 :: "r"(d), "l"(g), "r"(sz) : "memory");
                }
            }
            asm volatile("cp.async.commit_group;" ::: "memory");
        }
        asm volatile("cp.async.wait_group 1;" ::: "memory");
        __syncthreads();

        // ---- layer-0 A fragments from SMEM X ----
        {
            const float* xb = XB + cur * XB_BUF_FLOATS;
#pragma unroll
            for (int mt = 0; mt < 2; mt++) {
                int rr = warp * 32 + mt * 16 + td4;
                const float* p0 = xb + rr * XB_STRIDE + 2 * q;
                const float* p1 = p0 + 8 * XB_STRIDE;
#pragma unroll
                for (int kt = 0; kt < 2; kt++) {
                    float2 a = *(const float2*)(p0 + kt * 16);
                    float2 b = *(const float2*)(p1 + kt * 16);
                    float2 c = *(const float2*)(p0 + kt * 16 + 8);
                    float2 d = *(const float2*)(p1 + kt * 16 + 8);
                    A[mt][kt][0] = pack_h2(a.x, a.y);
                    A[mt][kt][1] = pack_h2(b.x, b.y);
                    A[mt][kt][2] = pack_h2(c.x, c.y);
                    A[mt][kt][3] = pack_h2(d.x, d.y);
                }
            }
        }
        __syncthreads();   // buffer-reuse safety

        // ---- 4 hidden layers; D(fp16) == next A, epilogue = HADD2+HMAX2 ----
#pragma unroll
        for (int l = 0; l < 4; l++) {
            const uint4* fh = FH + l * 16 * 32;
            if (l == 0) run_layer<2>(C, A, fh, lane);
            else        run_layer<4>(C, A, fh, lane);

            const uint32_t* bih = BIH + l * 32 + q;
#pragma unroll
            for (int i = 0; i < 4; i++) {
                uint32_t b20 = bih[(2 * i) * 4];
                uint32_t b21 = bih[(2 * i + 1) * 4];
#pragma unroll
                for (int mt = 0; mt < 2; mt++) {
                    A[mt][i][0] = h2_bias_relu(C[mt][2 * i][0],     b20);
                    A[mt][i][1] = h2_bias_relu(C[mt][2 * i][1],     b20);
                    A[mt][i][2] = h2_bias_relu(C[mt][2 * i + 1][0], b21);
                    A[mt][i][3] = h2_bias_relu(C[mt][2 * i + 1][1], b21);
                }
            }
        }

        // ---- final 64->3 as fp32-accum MMA (n padded to 8) + sigmoid ----
        {
            uint4 f0 = FH4[lane];
            uint4 f1 = FH4[32 + lane];
            float D0[4], D1[4];
            mma_f_init(D0, A[0][0], f0.x, f0.y);
            mma_f_init(D1, A[1][0], f0.x, f0.y);
            mma_f_acc(D0, A[0][1], f0.z, f0.w);
            mma_f_acc(D1, A[1][1], f0.z, f0.w);
            mma_f_acc(D0, A[0][2], f1.x, f1.y);
            mma_f_acc(D1, A[1][2], f1.x, f1.y);
            mma_f_acc(D0, A[0][3], f1.z, f1.w);
            mma_f_acc(D1, A[1][3], f1.z, f1.w);

            const float bc0 = B4p[2 * q];
            const float bc1 = B4p[2 * q + 1];
            const long rbase = (long)tile * 256 + warp * 32;
#pragma unroll
            for (int mt = 0; mt < 2; mt++) {
                const float* Dp = (mt == 0) ? D0 : D1;
                long r0 = rbase + mt * 16 + td4;
                long r1 = r0 + 8;
                float o0 = __fdividef(1.f, 1.f + __expf(-(Dp[0] + bc0)));
                float o1 = __fdividef(1.f, 1.f + __expf(-(Dp[1] + bc1)));
                float o2 = __fdividef(1.f, 1.f + __expf(-(Dp[2] + bc0)));
                float o3 = __fdividef(1.f, 1.f + __expf(-(Dp[3] + bc1)));
                if (q == 0) {
                    if (r0 < n) { out[r0 * 3 + 0] = o0; out[r0 * 3 + 1] = o1; }
                    if (r1 < n) { out[r1 * 3 + 0] = o2; out[r1 * 3 + 1] = o3; }
                } else if (q == 1) {
                    if (r0 < n) out[r0 * 3 + 2] = o0;
                    if (r1 < n) out[r1 * 3 + 2] = o2;
                }
            }
        }
    }
}

extern "C" void kernel_launch(void* const* d_in, const int* in_sizes, int n_in,
                              void* d_out, int out_size) {
    const float* x  = (const float*)d_in[0];
    const float* W0 = (const float*)d_in[1];
    const float* b0 = (const float*)d_in[2];
    const float* W1 = (const float*)d_in[3];
    const float* b1 = (const float*)d_in[4];
    const float* W2 = (const float*)d_in[5];
    const float* b2 = (const float*)d_in[6];
    const float* W3 = (const float*)d_in[7];
    const float* b3 = (const float*)d_in[8];
    const float* W4 = (const float*)d_in[9];
    const float* b4 = (const float*)d_in[10];
    float* out = (float*)d_out;

    const int n = in_sizes[0] / 32;
    const int ntiles = (n + 255) / 256;

    cudaFuncSetAttribute(mlp_hmma5_kernel,
                         cudaFuncAttributeMaxDynamicSharedMemorySize, SMEM_BYTES);

    int blocks = 148 * 2;
    if (ntiles < blocks) blocks = ntiles;

    mlp_hmma5_kernel<<<blocks, 256, SMEM_BYTES>>>(
        x, W0, b0, W1, b1, W2, b2, W3, b3, W4, b4, out, n, ntiles);
}

// round 12
// speedup vs baseline: 20.0280x; 1.1103x over previous
#include <cuda_runtime.h>
#include <cuda_fp16.h>
#include <stdint.h>
#include <math.h>

// ---------------------------------------------------------------------------
// Fused 5-layer MLP (32->64->64->64->64->3, ReLU hidden, sigmoid out).
// Hidden layers: mma.sync m16n8k16 fp16-in/fp16-accum; D-frag == next A-frag
// bitwise, epilogue = single fma.rn.relu.f16x2 per half2 (bias+ReLU fused).
// Final 64->3: fp32-accum MMA + sigmoid.
// NO CTA barriers in the main loop: each warp prefetches its own X slice via
// cp.async into a private double-buffered SMEM region and syncs with
// wait_group + syncwarp only -> warps drift, overlapping each other's MMAs.
// ---------------------------------------------------------------------------

#define FH_OFF     0           // 4l*4i*4kt*32lane*16B = 32768
#define XB_OFF     32768       // 8 warps * 2 bufs * 32 rows * 36 floats * 4B
#define XB_STRIDE  36
#define XW_FLOATS  (32 * XB_STRIDE)      // floats per warp-buffer (1152)
#define XW_BYTES   (XW_FLOATS * 4)       // 4608
#define FH4_OFF    106496      // final W4 frags: 2*32*16B = 1024 (XB is 73728)
#define BIH_OFF    107520      // bias half2: 4*32*4B = 512
#define B4P_OFF    108032      // 8 f32
#define SMEM_BYTES 108064

__device__ __forceinline__ void mma_h_acc(uint32_t c[2], const uint32_t a[4],
                                          uint32_t b0, uint32_t b1) {
    asm volatile(
        "mma.sync.aligned.m16n8k16.row.col.f16.f16.f16.f16 "
        "{%0,%1},{%2,%3,%4,%5},{%6,%7},{%0,%1};"
        : "+r"(c[0]), "+r"(c[1])
        : "r"(a[0]), "r"(a[1]), "r"(a[2]), "r"(a[3]), "r"(b0), "r"(b1));
}
__device__ __forceinline__ void mma_h_init(uint32_t c[2], const uint32_t a[4],
                                           uint32_t b0, uint32_t b1) {
    const uint32_t z = 0;
    asm volatile(
        "mma.sync.aligned.m16n8k16.row.col.f16.f16.f16.f16 "
        "{%0,%1},{%2,%3,%4,%5},{%6,%7},{%8,%8};"
        : "=r"(c[0]), "=r"(c[1])
        : "r"(a[0]), "r"(a[1]), "r"(a[2]), "r"(a[3]), "r"(b0), "r"(b1), "r"(z));
}
__device__ __forceinline__ void mma_f_acc(float c[4], const uint32_t a[4],
                                          uint32_t b0, uint32_t b1) {
    asm volatile(
        "mma.sync.aligned.m16n8k16.row.col.f32.f16.f16.f32 "
        "{%0,%1,%2,%3},{%4,%5,%6,%7},{%8,%9},{%0,%1,%2,%3};"
        : "+f"(c[0]), "+f"(c[1]), "+f"(c[2]), "+f"(c[3])
        : "r"(a[0]), "r"(a[1]), "r"(a[2]), "r"(a[3]), "r"(b0), "r"(b1));
}
__device__ __forceinline__ void mma_f_init(float c[4], const uint32_t a[4],
                                           uint32_t b0, uint32_t b1) {
    const float z = 0.f;
    asm volatile(
        "mma.sync.aligned.m16n8k16.row.col.f32.f16.f16.f32 "
        "{%0,%1,%2,%3},{%4,%5,%6,%7},{%8,%9},{%10,%10,%10,%10};"
        : "=f"(c[0]), "=f"(c[1]), "=f"(c[2]), "=f"(c[3])
        : "r"(a[0]), "r"(a[1]), "r"(a[2]), "r"(a[3]), "r"(b0), "r"(b1), "f"(z));
}

__device__ __forceinline__ uint32_t pack_h2(float v0, float v1) {
    uint32_t r;
    asm("cvt.rn.f16x2.f32 %0, %1, %2;" : "=r"(r) : "f"(v1), "f"(v0));
    return r;
}
// fused bias+ReLU: relu(h*1 + b) in ONE instruction (sm_80+)
__device__ __forceinline__ uint32_t h2_bias_relu(uint32_t h, uint32_t b) {
    uint32_t r;
    const uint32_t one = 0x3C003C00u;
    asm("fma.rn.relu.f16x2 %0, %1, %2, %3;" : "=r"(r) : "r"(h), "r"(one), "r"(b));
    return r;
}

template <int KT>
__device__ __forceinline__ void run_layer(uint32_t C[2][8][2],
                                          const uint32_t A[2][4][4],
                                          const uint4* __restrict__ fh,
                                          int lane) {
#pragma unroll
    for (int kt = 0; kt < KT; kt++) {
#pragma unroll
        for (int i = 0; i < 4; i++) {
            uint4 bh = fh[(i * 4 + kt) * 32 + lane];
            if (kt == 0) {
                mma_h_init(C[0][2 * i],     A[0][0], bh.x, bh.y);
                mma_h_init(C[0][2 * i + 1], A[0][0], bh.z, bh.w);
                mma_h_init(C[1][2 * i],     A[1][0], bh.x, bh.y);
                mma_h_init(C[1][2 * i + 1], A[1][0], bh.z, bh.w);
            } else {
                mma_h_acc(C[0][2 * i],     A[0][kt], bh.x, bh.y);
                mma_h_acc(C[0][2 * i + 1], A[0][kt], bh.z, bh.w);
                mma_h_acc(C[1][2 * i],     A[1][kt], bh.x, bh.y);
                mma_h_acc(C[1][2 * i + 1], A[1][kt], bh.z, bh.w);
            }
        }
    }
}

__global__ void __launch_bounds__(256, 2)
mlp_hmma6_kernel(const float* __restrict__ x,
                 const float* __restrict__ W0, const float* __restrict__ b0,
                 const float* __restrict__ W1, const float* __restrict__ b1,
                 const float* __restrict__ W2, const float* __restrict__ b2,
                 const float* __restrict__ W3, const float* __restrict__ b3,
                 const float* __restrict__ W4, const float* __restrict__ b4,
                 float* __restrict__ out, int n, int ntiles)
{
    extern __shared__ char sm[];
    uint4*    FH  = (uint4*)(sm + FH_OFF);
    float*    XB  = (float*)(sm + XB_OFF);
    uint4*    FH4 = (uint4*)(sm + FH4_OFF);
    uint32_t* BIH = (uint32_t*)(sm + BIH_OFF);
    float*    B4p = (float*)(sm + B4P_OFF);

    const int tid  = threadIdx.x;
    const int warp = tid >> 5;
    const int lane = tid & 31;
    const int q    = lane & 3;
    const int td4  = lane >> 2;

    // this warp's private double-buffered X region
    float* XW = XB + warp * 2 * XW_FLOATS;
    uint32_t xw_u32;
    asm("{ .reg .u64 t; cvta.to.shared.u64 t, %1; cvt.u32.u64 %0, t; }"
        : "=r"(xw_u32) : "l"((const void*)XW));

    // per-lane prefetch role: 8 iters, row = 4c + (lane>>3), seg = lane&7
    const int pf_rowoff = lane >> 3;
    const int pf_seg    = lane & 7;

    // ---- prefetch tile0 slice -> buf0 (per warp) ----
    {
        long rb = (long)blockIdx.x * 256 + warp * 32;
#pragma unroll
        for (int c = 0; c < 8; c++) {
            int row = 4 * c + pf_rowoff;
            long gr = rb + row;
            int ok = gr < n;
            const float* g = x + (ok ? gr : (long)(n - 1)) * 32 + pf_seg * 4;
            uint32_t d = xw_u32 + (uint32_t)(row * (XB_STRIDE * 4) + pf_seg * 16);
            int sz = ok ? 16 : 0;
            asm volatile("cp.async.cg.shared.global [%0], [%1], 16, %2;"
                         :: "r"(d), "l"(g), "r"(sz) : "memory");
        }
        asm volatile("cp.async.commit_group;" ::: "memory");
    }

    // ---- stage weights (whole CTA), then ONE barrier ----
    {
        const float* Ws[4] = {W0, W1, W2, W3};
        for (int idx = tid; idx < 4 * 4 * 4 * 32; idx += 256) {
            int ln = idx & 31;
            int kt = (idx >> 5) & 3;
            int i  = (idx >> 7) & 3;
            int l  = idx >> 9;
            int lq = ln & 3, ltd4 = ln >> 2;
            const int K = (l == 0) ? 32 : 64;
            const float* W = Ws[l];
            uint32_t rh[4];
#pragma unroll
            for (int r = 0; r < 4; r++) {
                int nn = 8 * (2 * i + (r >> 1)) + ltd4;
                int k  = 16 * kt + 2 * lq + (r & 1) * 8;
                float w0 = (k     < K) ? W[nn * K + k]     : 0.f;
                float w1 = (k + 1 < K) ? W[nn * K + k + 1] : 0.f;
                rh[r] = pack_h2(w0, w1);
            }
            FH[idx] = make_uint4(rh[0], rh[1], rh[2], rh[3]);
        }
        if (tid < 64) {
            int ktp = tid >> 5, ln = tid & 31;
            int lq = ln & 3, ltd4 = ln >> 2;
            uint32_t rh[4];
#pragma unroll
            for (int r = 0; r < 4; r++) {
                int kt = 2 * ktp + (r >> 1);
                int k  = 16 * kt + 2 * lq + (r & 1) * 8;
                float w0 = (ltd4 < 3) ? W4[ltd4 * 64 + k]     : 0.f;
                float w1 = (ltd4 < 3) ? W4[ltd4 * 64 + k + 1] : 0.f;
                rh[r] = pack_h2(w0, w1);
            }
            FH4[tid] = make_uint4(rh[0], rh[1], rh[2], rh[3]);
        }
        if (tid < 128) {
            int l = tid >> 5, idx = tid & 31;
            int nt = idx >> 2, bq = idx & 3;
            const float* bl = (l == 0) ? b0 : (l == 1) ? b1 : (l == 2) ? b2 : b3;
            BIH[tid] = pack_h2(bl[8 * nt + 2 * bq], bl[8 * nt + 2 * bq + 1]);
        }
        if (tid < 8) B4p[tid] = (tid < 3) ? b4[tid] : 0.f;
    }
    __syncthreads();   // weights visible; last CTA-wide barrier

    // hoist loop-invariant final-layer weight fragments
    const uint4 f0 = FH4[lane];
    const uint4 f1 = FH4[32 + lane];
    const float bc0 = B4p[2 * q];
    const float bc1 = B4p[2 * q + 1];

    uint32_t A[2][4][4];
    uint32_t C[2][8][2];

    int it = 0;
    for (int tile = blockIdx.x; tile < ntiles; tile += gridDim.x, it++) {
        const int cur = it & 1;

        // ---- prefetch next tile's slice into other buffer (this warp) ----
        {
            int nt_tile = tile + gridDim.x;
            if (nt_tile < ntiles) {
                long rb = (long)nt_tile * 256 + warp * 32;
                uint32_t bb = xw_u32 + (uint32_t)((cur ^ 1) * XW_BYTES);
#pragma unroll
                for (int c = 0; c < 8; c++) {
                    int row = 4 * c + pf_rowoff;
                    long gr = rb + row;
                    int ok = gr < n;
                    const float* g = x + (ok ? gr : (long)(n - 1)) * 32 + pf_seg * 4;
                    uint32_t d = bb + (uint32_t)(row * (XB_STRIDE * 4) + pf_seg * 16);
                    int sz = ok ? 16 : 0;
                    asm volatile("cp.async.cg.shared.global [%0], [%1], 16, %2;"
                                 :: "r"(d), "l"(g), "r"(sz) : "memory");
                }
            }
            asm volatile("cp.async.commit_group;" ::: "memory");
        }
        asm volatile("cp.async.wait_group 1;" ::: "memory");
        __syncwarp();   // warp-local visibility of cur buffer

        // ---- layer-0 A fragments from this warp's SMEM slice ----
        {
            const float* xb = XW + cur * XW_FLOATS;
#pragma unroll
            for (int mt = 0; mt < 2; mt++) {
                int rr = mt * 16 + td4;
                const float* p0 = xb + rr * XB_STRIDE + 2 * q;
                const float* p1 = p0 + 8 * XB_STRIDE;
#pragma unroll
                for (int kt = 0; kt < 2; kt++) {
                    float2 a = *(const float2*)(p0 + kt * 16);
                    float2 b = *(const float2*)(p1 + kt * 16);
                    float2 c = *(const float2*)(p0 + kt * 16 + 8);
                    float2 d = *(const float2*)(p1 + kt * 16 + 8);
                    A[mt][kt][0] = pack_h2(a.x, a.y);
                    A[mt][kt][1] = pack_h2(b.x, b.y);
                    A[mt][kt][2] = pack_h2(c.x, c.y);
                    A[mt][kt][3] = pack_h2(d.x, d.y);
                }
            }
        }
        __syncwarp();

        // ---- 4 hidden layers; epilogue = 1x fma.rn.relu.f16x2 per half2 ----
#pragma unroll
        for (int l = 0; l < 4; l++) {
            const uint4* fh = FH + l * 16 * 32;
            if (l == 0) run_layer<2>(C, A, fh, lane);
            else        run_layer<4>(C, A, fh, lane);

            const uint32_t* bih = BIH + l * 32 + q;
#pragma unroll
            for (int i = 0; i < 4; i++) {
                uint32_t b20 = bih[(2 * i) * 4];
                uint32_t b21 = bih[(2 * i + 1) * 4];
#pragma unroll
                for (int mt = 0; mt < 2; mt++) {
                    A[mt][i][0] = h2_bias_relu(C[mt][2 * i][0],     b20);
                    A[mt][i][1] = h2_bias_relu(C[mt][2 * i][1],     b20);
                    A[mt][i][2] = h2_bias_relu(C[mt][2 * i + 1][0], b21);
                    A[mt][i][3] = h2_bias_relu(C[mt][2 * i + 1][1], b21);
                }
            }
        }

        // ---- final 64->3 fp32-accum MMA + sigmoid + store ----
        {
            float D0[4], D1[4];
            mma_f_init(D0, A[0][0], f0.x, f0.y);
            mma_f_init(D1, A[1][0], f0.x, f0.y);
            mma_f_acc(D0, A[0][1], f0.z, f0.w);
            mma_f_acc(D1, A[1][1], f0.z, f0.w);
            mma_f_acc(D0, A[0][2], f1.x, f1.y);
            mma_f_acc(D1, A[1][2], f1.x, f1.y);
            mma_f_acc(D0, A[0][3], f1.z, f1.w);
            mma_f_acc(D1, A[1][3], f1.z, f1.w);

            const long rbase = (long)tile * 256 + warp * 32;
#pragma unroll
            for (int mt = 0; mt < 2; mt++) {
                const float* Dp = (mt == 0) ? D0 : D1;
                long r0 = rbase + mt * 16 + td4;
                long r1 = r0 + 8;
                float o0 = __fdividef(1.f, 1.f + __expf(-(Dp[0] + bc0)));
                float o1 = __fdividef(1.f, 1.f + __expf(-(Dp[1] + bc1)));
                float o2 = __fdividef(1.f, 1.f + __expf(-(Dp[2] + bc0)));
                float o3 = __fdividef(1.f, 1.f + __expf(-(Dp[3] + bc1)));
                if (q == 0) {
                    if (r0 < n) { out[r0 * 3 + 0] = o0; out[r0 * 3 + 1] = o1; }
                    if (r1 < n) { out[r1 * 3 + 0] = o2; out[r1 * 3 + 1] = o3; }
                } else if (q == 1) {
                    if (r0 < n) out[r0 * 3 + 2] = o0;
                    if (r1 < n) out[r1 * 3 + 2] = o2;
                }
            }
        }
    }
}

extern "C" void kernel_launch(void* const* d_in, const int* in_sizes, int n_in,
                              void* d_out, int out_size) {
    const float* x  = (const float*)d_in[0];
    const float* W0 = (const float*)d_in[1];
    const float* b0 = (const float*)d_in[2];
    const float* W1 = (const float*)d_in[3];
    const float* b1 = (const float*)d_in[4];
    const float* W2 = (const float*)d_in[5];
    const float* b2 = (const float*)d_in[6];
    const float* W3 = (const float*)d_in[7];
    const float* b3 = (const float*)d_in[8];
    const float* W4 = (const float*)d_in[9];
    const float* b4 = (const float*)d_in[10];
    float* out = (float*)d_out;

    const int n = in_sizes[0] / 32;
    const int ntiles = (n + 255) / 256;

    cudaFuncSetAttribute(mlp_hmma6_kernel,
                         cudaFuncAttributeMaxDynamicSharedMemorySize, SMEM_BYTES);

    int blocks = 148 * 2;
    if (ntiles < blocks) blocks = ntiles;

    mlp_hmma6_kernel<<<blocks, 256, SMEM_BYTES>>>(
        x, W0, b0, W1, b1, W2, b2, W3, b3, W4, b4, out, n, ntiles);
}

// round 13
// speedup vs baseline: 20.1920x; 1.0082x over previous
#include <cuda_runtime.h>
#include <cuda_fp16.h>
#include <stdint.h>
#include <math.h>

// ---------------------------------------------------------------------------
// Fused 5-layer MLP (32->64->64->64->64->3, ReLU hidden, sigmoid out).
// mma.sync m16n8k16 fp16-in/fp16-accum hidden layers (D-frag == next A-frag),
// fused fma.rn.relu.f16x2 epilogues, fp32-accum final MMA + sigmoid.
// This round: (1) one-time warp phase-stagger (anti-phase the 4 warps per
// SMSP so tensor bursts interleave instead of locking step), (2) software-
// pipelined tile tail: cp.async wait + next-tile A-build overlap the sigmoid
// and store chain of the current tile.
// ---------------------------------------------------------------------------

#define FH_OFF     0           // 4l*4i*4kt*32lane*16B = 32768
#define XB_OFF     32768       // 8 warps * 2 bufs * 32 rows * 36 floats * 4B
#define XB_STRIDE  36
#define XW_FLOATS  (32 * XB_STRIDE)      // 1152 floats per warp-buffer
#define XW_BYTES   (XW_FLOATS * 4)       // 4608
#define FH4_OFF    106496
#define BIH_OFF    107520
#define B4P_OFF    108032
#define SMEM_BYTES 108064

__device__ __forceinline__ void mma_h_acc(uint32_t c[2], const uint32_t a[4],
                                          uint32_t b0, uint32_t b1) {
    asm volatile(
        "mma.sync.aligned.m16n8k16.row.col.f16.f16.f16.f16 "
        "{%0,%1},{%2,%3,%4,%5},{%6,%7},{%0,%1};"
        : "+r"(c[0]), "+r"(c[1])
        : "r"(a[0]), "r"(a[1]), "r"(a[2]), "r"(a[3]), "r"(b0), "r"(b1));
}
__device__ __forceinline__ void mma_h_init(uint32_t c[2], const uint32_t a[4],
                                           uint32_t b0, uint32_t b1) {
    const uint32_t z = 0;
    asm volatile(
        "mma.sync.aligned.m16n8k16.row.col.f16.f16.f16.f16 "
        "{%0,%1},{%2,%3,%4,%5},{%6,%7},{%8,%8};"
        : "=r"(c[0]), "=r"(c[1])
        : "r"(a[0]), "r"(a[1]), "r"(a[2]), "r"(a[3]), "r"(b0), "r"(b1), "r"(z));
}
__device__ __forceinline__ void mma_f_acc(float c[4], const uint32_t a[4],
                                          uint32_t b0, uint32_t b1) {
    asm volatile(
        "mma.sync.aligned.m16n8k16.row.col.f32.f16.f16.f32 "
        "{%0,%1,%2,%3},{%4,%5,%6,%7},{%8,%9},{%0,%1,%2,%3};"
        : "+f"(c[0]), "+f"(c[1]), "+f"(c[2]), "+f"(c[3])
        : "r"(a[0]), "r"(a[1]), "r"(a[2]), "r"(a[3]), "r"(b0), "r"(b1));
}
__device__ __forceinline__ void mma_f_init(float c[4], const uint32_t a[4],
                                           uint32_t b0, uint32_t b1) {
    const float z = 0.f;
    asm volatile(
        "mma.sync.aligned.m16n8k16.row.col.f32.f16.f16.f32 "
        "{%0,%1,%2,%3},{%4,%5,%6,%7},{%8,%9},{%10,%10,%10,%10};"
        : "=f"(c[0]), "=f"(c[1]), "=f"(c[2]), "=f"(c[3])
        : "r"(a[0]), "r"(a[1]), "r"(a[2]), "r"(a[3]), "r"(b0), "r"(b1), "f"(z));
}

__device__ __forceinline__ uint32_t pack_h2(float v0, float v1) {
    uint32_t r;
    asm("cvt.rn.f16x2.f32 %0, %1, %2;" : "=r"(r) : "f"(v1), "f"(v0));
    return r;
}
__device__ __forceinline__ uint32_t h2_bias_relu(uint32_t h, uint32_t b) {
    uint32_t r;
    const uint32_t one = 0x3C003C00u;
    asm("fma.rn.relu.f16x2 %0, %1, %2, %3;" : "=r"(r) : "r"(h), "r"(one), "r"(b));
    return r;
}

template <int KT>
__device__ __forceinline__ void run_layer(uint32_t C[2][8][2],
                                          const uint32_t A[2][4][4],
                                          const uint4* __restrict__ fh,
                                          int lane) {
#pragma unroll
    for (int kt = 0; kt < KT; kt++) {
#pragma unroll
        for (int i = 0; i < 4; i++) {
            uint4 bh = fh[(i * 4 + kt) * 32 + lane];
            if (kt == 0) {
                mma_h_init(C[0][2 * i],     A[0][0], bh.x, bh.y);
                mma_h_init(C[0][2 * i + 1], A[0][0], bh.z, bh.w);
                mma_h_init(C[1][2 * i],     A[1][0], bh.x, bh.y);
                mma_h_init(C[1][2 * i + 1], A[1][0], bh.z, bh.w);
            } else {
                mma_h_acc(C[0][2 * i],     A[0][kt], bh.x, bh.y);
                mma_h_acc(C[0][2 * i + 1], A[0][kt], bh.z, bh.w);
                mma_h_acc(C[1][2 * i],     A[1][kt], bh.x, bh.y);
                mma_h_acc(C[1][2 * i + 1], A[1][kt], bh.z, bh.w);
            }
        }
    }
}

// issue cp.async for one warp's 32-row slice + commit
__device__ __forceinline__ void prefetch_slice(const float* __restrict__ x,
                                               long rb, int n, uint32_t dst,
                                               int rowoff, int seg) {
#pragma unroll
    for (int c = 0; c < 8; c++) {
        int row = 4 * c + rowoff;
        long gr = rb + row;
        int ok = gr < n;
        const float* g = x + (ok ? gr : (long)(n - 1)) * 32 + seg * 4;
        uint32_t d = dst + (uint32_t)(row * (XB_STRIDE * 4) + seg * 16);
        int sz = ok ? 16 : 0;
        asm volatile("cp.async.cg.shared.global [%0], [%1], 16, %2;"
                     :: "r"(d), "l"(g), "r"(sz) : "memory");
    }
    asm volatile("cp.async.commit_group;" ::: "memory");
}

__device__ __forceinline__ void build_A(uint32_t A[2][4][4],
                                        const float* __restrict__ xb,
                                        int td4, int q) {
#pragma unroll
    for (int mt = 0; mt < 2; mt++) {
        int rr = mt * 16 + td4;
        const float* p0 = xb + rr * XB_STRIDE + 2 * q;
        const float* p1 = p0 + 8 * XB_STRIDE;
#pragma unroll
        for (int kt = 0; kt < 2; kt++) {
            float2 a = *(const float2*)(p0 + kt * 16);
            float2 b = *(const float2*)(p1 + kt * 16);
            float2 c = *(const float2*)(p0 + kt * 16 + 8);
            float2 d = *(const float2*)(p1 + kt * 16 + 8);
            A[mt][kt][0] = pack_h2(a.x, a.y);
            A[mt][kt][1] = pack_h2(b.x, b.y);
            A[mt][kt][2] = pack_h2(c.x, c.y);
            A[mt][kt][3] = pack_h2(d.x, d.y);
        }
    }
}

__global__ void __launch_bounds__(256, 2)
mlp_hmma7_kernel(const float* __restrict__ x,
                 const float* __restrict__ W0, const float* __restrict__ b0,
                 const float* __restrict__ W1, const float* __restrict__ b1,
                 const float* __restrict__ W2, const float* __restrict__ b2,
                 const float* __restrict__ W3, const float* __restrict__ b3,
                 const float* __restrict__ W4, const float* __restrict__ b4,
                 float* __restrict__ out, int n, int ntiles)
{
    extern __shared__ char sm[];
    uint4*    FH  = (uint4*)(sm + FH_OFF);
    float*    XB  = (float*)(sm + XB_OFF);
    uint4*    FH4 = (uint4*)(sm + FH4_OFF);
    uint32_t* BIH = (uint32_t*)(sm + BIH_OFF);
    float*    B4p = (float*)(sm + B4P_OFF);

    const int tid  = threadIdx.x;
    const int warp = tid >> 5;
    const int lane = tid & 31;
    const int q    = lane & 3;
    const int td4  = lane >> 2;

    float* XW = XB + warp * 2 * XW_FLOATS;
    uint32_t xw_u32;
    asm("{ .reg .u64 t; cvta.to.shared.u64 t, %1; cvt.u32.u64 %0, t; }"
        : "=r"(xw_u32) : "l"((const void*)XW));

    const int pf_rowoff = lane >> 3;
    const int pf_seg    = lane & 7;

    // ---- prefetch tile0 slice -> buf0 (per warp) ----
    prefetch_slice(x, (long)blockIdx.x * 256 + warp * 32, n, xw_u32,
                   pf_rowoff, pf_seg);

    // ---- stage weights (whole CTA), one barrier ----
    {
        const float* Ws[4] = {W0, W1, W2, W3};
        for (int idx = tid; idx < 4 * 4 * 4 * 32; idx += 256) {
            int ln = idx & 31;
            int kt = (idx >> 5) & 3;
            int i  = (idx >> 7) & 3;
            int l  = idx >> 9;
            int lq = ln & 3, ltd4 = ln >> 2;
            const int K = (l == 0) ? 32 : 64;
            const float* W = Ws[l];
            uint32_t rh[4];
#pragma unroll
            for (int r = 0; r < 4; r++) {
                int nn = 8 * (2 * i + (r >> 1)) + ltd4;
                int k  = 16 * kt + 2 * lq + (r & 1) * 8;
                float w0 = (k     < K) ? W[nn * K + k]     : 0.f;
                float w1 = (k + 1 < K) ? W[nn * K + k + 1] : 0.f;
                rh[r] = pack_h2(w0, w1);
            }
            FH[idx] = make_uint4(rh[0], rh[1], rh[2], rh[3]);
        }
        if (tid < 64) {
            int ktp = tid >> 5, ln = tid & 31;
            int lq = ln & 3, ltd4 = ln >> 2;
            uint32_t rh[4];
#pragma unroll
            for (int r = 0; r < 4; r++) {
                int kt = 2 * ktp + (r >> 1);
                int k  = 16 * kt + 2 * lq + (r & 1) * 8;
                float w0 = (ltd4 < 3) ? W4[ltd4 * 64 + k]     : 0.f;
                float w1 = (ltd4 < 3) ? W4[ltd4 * 64 + k + 1] : 0.f;
                rh[r] = pack_h2(w0, w1);
            }
            FH4[tid] = make_uint4(rh[0], rh[1], rh[2], rh[3]);
        }
        if (tid < 128) {
            int l = tid >> 5, idx = tid & 31;
            int nt = idx >> 2, bq = idx & 3;
            const float* bl = (l == 0) ? b0 : (l == 1) ? b1 : (l == 2) ? b2 : b3;
            BIH[tid] = pack_h2(bl[8 * nt + 2 * bq], bl[8 * nt + 2 * bq + 1]);
        }
        if (tid < 8) B4p[tid] = (tid < 3) ? b4[tid] : 0.f;
    }
    __syncthreads();

    // ---- one-time phase stagger: anti-phase the 4 warps on each SMSP ----
    {
        int wave  = (blockIdx.x >= 148) ? 1 : 0;       // co-resident CTA parity
        int phase = (((warp >> 2) & 1) << 1) | wave;   // 0..3
        if (phase) {
            long long t0 = clock64();
            long long d  = (long long)phase * 1500;
            while (clock64() - t0 < d) { }
        }
    }

    const uint4 f0 = FH4[lane];
    const uint4 f1 = FH4[32 + lane];
    const float bc0 = B4p[2 * q];
    const float bc1 = B4p[2 * q + 1];

    uint32_t A[2][4][4];
    uint32_t C[2][8][2];

    // ---- prologue: A for tile0, start tile1 prefetch ----
    asm volatile("cp.async.wait_group 0;" ::: "memory");
    __syncwarp();
    build_A(A, XW, td4, q);
    {
        long t1 = (long)blockIdx.x + gridDim.x;
        if (t1 < ntiles)
            prefetch_slice(x, t1 * 256 + warp * 32, n, xw_u32 + XW_BYTES,
                           pf_rowoff, pf_seg);
    }

    int it = 0;
    for (int tile = blockIdx.x; tile < ntiles; tile += gridDim.x, it++) {
        const int cur = it & 1;

        // ---- 4 hidden layers on register-resident A ----
#pragma unroll
        for (int l = 0; l < 4; l++) {
            const uint4* fh = FH + l * 16 * 32;
            if (l == 0) run_layer<2>(C, A, fh, lane);
            else        run_layer<4>(C, A, fh, lane);

            const uint32_t* bih = BIH + l * 32 + q;
#pragma unroll
            for (int i = 0; i < 4; i++) {
                uint32_t b20 = bih[(2 * i) * 4];
                uint32_t b21 = bih[(2 * i + 1) * 4];
#pragma unroll
                for (int mt = 0; mt < 2; mt++) {
                    A[mt][i][0] = h2_bias_relu(C[mt][2 * i][0],     b20);
                    A[mt][i][1] = h2_bias_relu(C[mt][2 * i][1],     b20);
                    A[mt][i][2] = h2_bias_relu(C[mt][2 * i + 1][0], b21);
                    A[mt][i][3] = h2_bias_relu(C[mt][2 * i + 1][1], b21);
                }
            }
        }

        // ---- final 64->3 fp32-accum MMA ----
        float D0[4], D1[4];
        mma_f_init(D0, A[0][0], f0.x, f0.y);
        mma_f_init(D1, A[1][0], f0.x, f0.y);
        mma_f_acc(D0, A[0][1], f0.z, f0.w);
        mma_f_acc(D1, A[1][1], f0.z, f0.w);
        mma_f_acc(D0, A[0][2], f1.x, f1.y);
        mma_f_acc(D1, A[1][2], f1.x, f1.y);
        mma_f_acc(D0, A[0][3], f1.z, f1.w);
        mma_f_acc(D1, A[1][3], f1.z, f1.w);

        // ---- overlapped tail: wait next X, rebuild A, prefetch tile+2s ----
        asm volatile("cp.async.wait_group 0;" ::: "memory");
        __syncwarp();
        if (tile + gridDim.x < ntiles)
            build_A(A, XW + (cur ^ 1) * XW_FLOATS, td4, q);
        {
            long t2 = (long)tile + 2L * gridDim.x;
            if (t2 < ntiles)
                prefetch_slice(x, t2 * 256 + warp * 32, n,
                               xw_u32 + (uint32_t)cur * XW_BYTES,
                               pf_rowoff, pf_seg);
        }

        // ---- sigmoid + store (overlaps the A-build latency above) ----
        {
            const long rbase = (long)tile * 256 + warp * 32;
#pragma unroll
            for (int mt = 0; mt < 2; mt++) {
                const float* Dp = (mt == 0) ? D0 : D1;
                long r0 = rbase + mt * 16 + td4;
                long r1 = r0 + 8;
                float o0 = __fdividef(1.f, 1.f + __expf(-(Dp[0] + bc0)));
                float o1 = __fdividef(1.f, 1.f + __expf(-(Dp[1] + bc1)));
                float o2 = __fdividef(1.f, 1.f + __expf(-(Dp[2] + bc0)));
                float o3 = __fdividef(1.f, 1.f + __expf(-(Dp[3] + bc1)));
                if (q == 0) {
                    if (r0 < n) { out[r0 * 3 + 0] = o0; out[r0 * 3 + 1] = o1; }
                    if (r1 < n) { out[r1 * 3 + 0] = o2; out[r1 * 3 + 1] = o3; }
                } else if (q == 1) {
                    if (r0 < n) out[r0 * 3 + 2] = o0;
                    if (r1 < n) out[r1 * 3 + 2] = o2;
                }
            }
        }
    }
}

extern "C" void kernel_launch(void* const* d_in, const int* in_sizes, int n_in,
                              void* d_out, int out_size) {
    const float* x  = (const float*)d_in[0];
    const float* W0 = (const float*)d_in[1];
    const float* b0 = (const float*)d_in[2];
    const float* W1 = (const float*)d_in[3];
    const float* b1 = (const float*)d_in[4];
    const float* W2 = (const float*)d_in[5];
    const float* b2 = (const float*)d_in[6];
    const float* W3 = (const float*)d_in[7];
    const float* b3 = (const float*)d_in[8];
    const float* W4 = (const float*)d_in[9];
    const float* b4 = (const float*)d_in[10];
    float* out = (float*)d_out;

    const int n = in_sizes[0] / 32;
    const int ntiles = (n + 255) / 256;

    cudaFuncSetAttribute(mlp_hmma7_kernel,
                         cudaFuncAttributeMaxDynamicSharedMemorySize, SMEM_BYTES);

    int blocks = 148 * 2;
    if (ntiles < blocks) blocks = ntiles;

    mlp_hmma7_kernel<<<blocks, 256, SMEM_BYTES>>>(
        x, W0, b0, W1, b1, W2, b2, W3, b3, W4, b4, out, n, ntiles);
}